// round 11
// baseline (speedup 1.0000x reference)
#include <cuda_runtime.h>
#include <cstdint>

#define SEQ   4096
#define VECT  300
#define HID   128
#define G3    384
#define NSTACK 3

typedef unsigned long long ull;
typedef long long ll;

// ---------------------------------------------------------------------------
// Scratch (static device globals — allocation-free)
// ---------------------------------------------------------------------------
__device__ float g_x    [2 * SEQ * VECT];
__device__ float g_cur  [2 * SEQ * VECT];
__device__ float g_qkv  [2ll * SEQ * 3 * VECT];   // packed [seq][row][900]: Q|K|V
__device__ float g_vt   [2 * SEQ * VECT];         // V^T per seq: [VECT][SEQ]
__device__ float g_attn [2 * SEQ * VECT];
__device__ float g_h    [2 * SEQ * VECT];
__device__ float g_tmp  [2 * SEQ * VECT];
__device__ float g_scores[2ll * SEQ * SEQ];
__device__ float g_gx   [2 * SEQ * G3];
__device__ float g_hcat [2 * HID];
// packed weights
__device__ float g_wqkv [3 * VECT * VECT];
__device__ float g_bqkv [3 * VECT];
__device__ float g_wih  [2 * G3 * VECT];
__device__ float g_bih  [2 * G3];

// ---------------------------------------------------------------------------
__global__ void init_kernel(const float* __restrict__ x1, const float* __restrict__ x2)
{
    int i = blockIdx.x * blockDim.x + threadIdx.x;
    const int n = SEQ * VECT;
    if (i < n) {
        float v = x1[i];
        g_x[i] = v; g_cur[i] = v;
    } else if (i < 2 * n) {
        float v = x2[i - n];
        g_x[i] = v; g_cur[i] = v;
    }
}

// ---------------------------------------------------------------------------
__global__ void pack_kernel(
    const float* __restrict__ qw, const float* __restrict__ qb,
    const float* __restrict__ kw, const float* __restrict__ kb,
    const float* __restrict__ vw, const float* __restrict__ vb,
    const float* __restrict__ w1, const float* __restrict__ b1,
    const float* __restrict__ w2, const float* __restrict__ b2)
{
    const int N1 = 3 * VECT * VECT;
    const int N2 = 3 * VECT;
    const int N3 = 2 * G3 * VECT;
    const int N4 = 2 * G3;
    int i = blockIdx.x * blockDim.x + threadIdx.x;
    if (i < N1) {
        int row = i / VECT, col = i % VECT;
        float v;
        if (row < VECT)            v = qw[row * VECT + col];
        else if (row < 2 * VECT)   v = kw[(row - VECT) * VECT + col];
        else                       v = vw[(row - 2 * VECT) * VECT + col];
        g_wqkv[i] = v;
    } else if (i < N1 + N2) {
        int r = i - N1;
        g_bqkv[r] = (r < VECT) ? qb[r] : (r < 2 * VECT) ? kb[r - VECT] : vb[r - 2 * VECT];
    } else if (i < N1 + N2 + N3) {
        int j = i - N1 - N2;
        g_wih[j] = (j < G3 * VECT) ? w1[j] : w2[j - G3 * VECT];
    } else if (i < N1 + N2 + N3 + N4) {
        int j = i - N1 - N2 - N3;
        g_bih[j] = (j < G3) ? b1[j] : b2[j - G3];
    }
}

// ---------------------------------------------------------------------------
// Transpose: dst[c][r] = src[r][c]. src [SEQ, VECT] (ld=lds), dst [VECT][SEQ].
// ---------------------------------------------------------------------------
__global__ __launch_bounds__(256) void transpose_kernel(
    const float* __restrict__ src, float* __restrict__ dst,
    int lds, ll sSrc, ll sDst)
{
    __shared__ float t[32][33];
    src += (ll)blockIdx.z * sSrc;
    dst += (ll)blockIdx.z * sDst;
    const int r0 = blockIdx.y * 32, c0 = blockIdx.x * 32;
    const int x = threadIdx.x & 31, y = threadIdx.x >> 5;

    #pragma unroll
    for (int i = 0; i < 4; i++) {
        int col = c0 + x;
        if (col < VECT) t[y + 8 * i][x] = src[(size_t)(r0 + y + 8 * i) * lds + col];
    }
    __syncthreads();
    #pragma unroll
    for (int i = 0; i < 4; i++) {
        int c = c0 + y + 8 * i;
        if (c < VECT) dst[(size_t)c * SEQ + r0 + x] = t[x][y + 8 * i];
    }
}

// ---------------------------------------------------------------------------
// MMA helpers
// ---------------------------------------------------------------------------
__device__ __forceinline__ unsigned smem_u32(const void* p)
{
    return (unsigned)__cvta_generic_to_shared(p);
}
__device__ __forceinline__ void cp_async16(unsigned dst, const float* src, bool valid)
{
    int sz = valid ? 16 : 0;   // src-size 0 -> zero-fill 16B
    asm volatile("cp.async.cg.shared.global [%0], [%1], 16, %2;\n"
                 :: "r"(dst), "l"(src), "r"(sz));
}
__device__ __forceinline__ void ldsm_x4(uint32_t* r, unsigned addr)
{
    asm volatile("ldmatrix.sync.aligned.m8n8.x4.shared.b16 {%0,%1,%2,%3}, [%4];"
                 : "=r"(r[0]), "=r"(r[1]), "=r"(r[2]), "=r"(r[3]) : "r"(addr));
}
__device__ __forceinline__ void mma8(float* c, const uint32_t* a, const uint32_t* b)
{
    asm volatile(
        "mma.sync.aligned.m16n8k8.row.col.f32.tf32.tf32.f32 "
        "{%0,%1,%2,%3}, {%4,%5,%6,%7}, {%8,%9}, {%0,%1,%2,%3};"
        : "+f"(c[0]), "+f"(c[1]), "+f"(c[2]), "+f"(c[3])
        : "r"(a[0]), "r"(a[1]), "r"(a[2]), "r"(a[3]), "r"(b[0]), "r"(b[1]));
}

// ---------------------------------------------------------------------------
// TF32 GEMM: C[M,N] = alpha*A[M,K]*B[N,K]^T (+bias), 128x128x32, 3-stage.
// M % 128 == 0 assumed.
// ---------------------------------------------------------------------------
__global__ __launch_bounds__(256, 2) void mma_bt(
    const float* __restrict__ A, const float* __restrict__ B, float* __restrict__ C,
    int M, int N, int K, int lda, int ldb, int ldc,
    ll sAb, ll sBb, ll sCb,
    const float* __restrict__ bias, ll sBiasb, float alpha)
{
    constexpr int BM = 128, BN = 128, BK = 32, AP = 36;
    constexpr int ASZ = BM * AP;
    constexpr int STG = 2 * ASZ;

    extern __shared__ float sm[];

    A += (ll)blockIdx.z * sAb;
    B += (ll)blockIdx.z * sBb;
    C += (ll)blockIdx.z * sCb;
    if (bias) bias += (ll)blockIdx.z * sBiasb;

    const int m0 = blockIdx.y * BM, n0 = blockIdx.x * BN;
    const int tid = threadIdx.x, lane = tid & 31, warp = tid >> 5;
    const int g = lane >> 2, tg = lane & 3;
    const int wm = (warp & 1) * 64, wn = (warp >> 1) * 32;

    const int lm   = lane >> 3;
    const int lrow = (lm & 1) * 8 + (lane & 7);
    const int lcol = (lm >> 1) * 4;

    float acc[4][4][4] = {};
    const int nk = (K + BK - 1) / BK;

    auto load_stage = [&](int s, int k0) {
        unsigned base = smem_u32(sm + s * STG);
        #pragma unroll
        for (int i = 0; i < 4; i++) {
            int idx = tid + i * 256;
            int r = idx >> 3, c = (idx & 7) * 4;
            cp_async16(base + (unsigned)(r * AP + c) * 4,
                       A + (size_t)(m0 + r) * lda + k0 + c, (k0 + c < K));
        }
        #pragma unroll
        for (int i = 0; i < 4; i++) {
            int idx = tid + i * 256;
            int r = idx >> 3, c = (idx & 7) * 4;
            bool v = (n0 + r < N) && (k0 + c < K);
            cp_async16(base + (unsigned)(ASZ + r * AP + c) * 4,
                       B + (size_t)(n0 + r) * ldb + k0 + c, v);
        }
        asm volatile("cp.async.commit_group;");
    };

    load_stage(0, 0);
    if (nk > 1) load_stage(1, BK);

    for (int kt = 0; kt < nk; kt++) {
        int s = kt % 3;
        if (kt + 1 < nk) asm volatile("cp.async.wait_group 1;");
        else             asm volatile("cp.async.wait_group 0;");
        __syncthreads();

        if (kt + 2 < nk) load_stage((kt + 2) % 3, (kt + 2) * BK);

        unsigned aBase = smem_u32(sm + s * STG)
                       + (unsigned)((wm + lrow) * AP + lcol) * 4;
        unsigned bBase = smem_u32(sm + s * STG + ASZ)
                       + (unsigned)((wn + lrow) * AP + lcol) * 4;

        #pragma unroll
        for (int kk = 0; kk < BK; kk += 8) {
            uint32_t ar[4][4];
            #pragma unroll
            for (int mt = 0; mt < 4; mt++)
                ldsm_x4(ar[mt], aBase + (unsigned)(mt * 16 * AP + kk) * 4);
            uint32_t brq[2][4];
            #pragma unroll
            for (int nh = 0; nh < 2; nh++)
                ldsm_x4(brq[nh], bBase + (unsigned)(nh * 16 * AP + kk) * 4);

            #pragma unroll
            for (int mt = 0; mt < 4; mt++) {
                #pragma unroll
                for (int nt = 0; nt < 4; nt++) {
                    uint32_t bb[2] = { brq[nt >> 1][nt & 1], brq[nt >> 1][(nt & 1) + 2] };
                    mma8(acc[mt][nt], ar[mt], bb);
                }
            }
        }
    }

    #pragma unroll
    for (int mt = 0; mt < 4; mt++) {
        #pragma unroll
        for (int nt = 0; nt < 4; nt++) {
            int row0 = m0 + wm + mt * 16 + g;
            int col  = n0 + wn + nt * 8 + 2 * tg;
            if (col + 1 < N) {
                float b0 = bias ? bias[col]     : 0.f;
                float b1 = bias ? bias[col + 1] : 0.f;
                float2 v0 = make_float2(alpha * acc[mt][nt][0] + b0,
                                        alpha * acc[mt][nt][1] + b1);
                float2 v1 = make_float2(alpha * acc[mt][nt][2] + b0,
                                        alpha * acc[mt][nt][3] + b1);
                *reinterpret_cast<float2*>(C + (size_t)row0 * ldc + col) = v0;
                *reinterpret_cast<float2*>(C + (size_t)(row0 + 8) * ldc + col) = v1;
            } else if (col < N) {
                float b0 = bias ? bias[col] : 0.f;
                C[(size_t)row0 * ldc + col]       = alpha * acc[mt][nt][0] + b0;
                C[(size_t)(row0 + 8) * ldc + col] = alpha * acc[mt][nt][2] + b0;
            }
        }
    }
}

// ---------------------------------------------------------------------------
__device__ __forceinline__ float warp_max(float v) {
    #pragma unroll
    for (int o = 16; o > 0; o >>= 1) v = fmaxf(v, __shfl_xor_sync(0xffffffffu, v, o));
    return v;
}
__device__ __forceinline__ float warp_sum(float v) {
    #pragma unroll
    for (int o = 16; o > 0; o >>= 1) v += __shfl_xor_sync(0xffffffffu, v, o);
    return v;
}

__global__ __launch_bounds__(256) void softmax_kernel(float* __restrict__ Sm)
{
    size_t off = ((size_t)blockIdx.y * SEQ + blockIdx.x) * SEQ;
    float4* row4 = reinterpret_cast<float4*>(Sm + off);
    const int t = threadIdx.x;
    const int lane = t & 31, wid = t >> 5;

    float4 v[4];
    #pragma unroll
    for (int i = 0; i < 4; i++) v[i] = row4[t + 256 * i];

    float m = -3.4e38f;
    #pragma unroll
    for (int i = 0; i < 4; i++)
        m = fmaxf(m, fmaxf(fmaxf(v[i].x, v[i].y), fmaxf(v[i].z, v[i].w)));

    __shared__ float red[8];
    m = warp_max(m);
    if (lane == 0) red[wid] = m;
    __syncthreads();
    float bm = red[0];
    #pragma unroll
    for (int k = 1; k < 8; k++) bm = fmaxf(bm, red[k]);

    float s = 0.f;
    #pragma unroll
    for (int i = 0; i < 4; i++) {
        v[i].x = __expf(v[i].x - bm); v[i].y = __expf(v[i].y - bm);
        v[i].z = __expf(v[i].z - bm); v[i].w = __expf(v[i].w - bm);
        s += v[i].x + v[i].y + v[i].z + v[i].w;
    }
    s = warp_sum(s);
    __syncthreads();
    if (lane == 0) red[wid] = s;
    __syncthreads();
    float bs = 0.f;
    #pragma unroll
    for (int k = 0; k < 8; k++) bs += red[k];
    float inv = 1.f / bs;

    #pragma unroll
    for (int i = 0; i < 4; i++) {
        v[i].x *= inv; v[i].y *= inv; v[i].z *= inv; v[i].w *= inv;
        row4[t + 256 * i] = v[i];
    }
}

// ---------------------------------------------------------------------------
__global__ __launch_bounds__(128) void ln_add_kernel(
    const float* __restrict__ s1, const float* __restrict__ s2,
    const float* __restrict__ g, const float* __restrict__ b,
    float* __restrict__ dst)
{
    const int wid = threadIdx.x >> 5, lane = threadIdx.x & 31;
    const int row = blockIdx.x * 4 + wid;
    const size_t base = ((size_t)blockIdx.y * SEQ + row) * VECT;

    float v[10];
    float s = 0.f;
    #pragma unroll
    for (int i = 0; i < 10; i++) {
        int j = lane + 32 * i;
        float x = 0.f;
        if (j < VECT) x = s1[base + j] + s2[base + j];
        v[i] = x; s += x;
    }
    s = warp_sum(s);
    float mean = s * (1.f / VECT);

    float var = 0.f;
    #pragma unroll
    for (int i = 0; i < 10; i++) {
        int j = lane + 32 * i;
        if (j < VECT) { float d = v[i] - mean; var += d * d; }
    }
    var = warp_sum(var) * (1.f / VECT);
    float inv = rsqrtf(var + 1e-5f);

    #pragma unroll
    for (int i = 0; i < 10; i++) {
        int j = lane + 32 * i;
        if (j < VECT) dst[base + j] = g[j] * (v[i] - mean) * inv + b[j];
    }
}

// ---------------------------------------------------------------------------
// GRU recurrence v3. 2 blocks (one per GRU), 768 threads (2 per gate-row).
// Thread pair (lanes 2k, 2k+1) each compute a 64-dim half-dot (4 chains of
// 8 FFMA2) and combine via shfl_xor(1). 6 warps/SMSP for latency hiding.
// Input gx read with a 2-step register lookahead pipeline (covers DRAM).
// r/z sigmoids pre-barrier; n-threads own h in registers.
// ---------------------------------------------------------------------------
__global__ __launch_bounds__(768, 1) void gru_kernel(
    const float* __restrict__ whh1, const float* __restrict__ bhh1,
    const float* __restrict__ whh2, const float* __restrict__ bhh2)
{
    const int b = blockIdx.x;
    const float* whh = b ? whh2 : whh1;
    const float* bhh = b ? bhh2 : bhh1;
    const float* gx  = g_gx + (size_t)b * SEQ * G3;
    const int t = threadIdx.x;           // 0..767
    const int row  = t >> 1;             // 0..383 (gate-row)
    const int half = t & 1;              // which 64-dim half
    const int gate = row >> 7;           // 0=r, 1=z, 2=n
    const int hid  = row & 127;

    // this thread's half of w_hh row: 64 floats = 32 f32x2 pairs
    ull wp[32];
    const ull* w2 = reinterpret_cast<const ull*>(whh + row * HID + half * 64);
    #pragma unroll
    for (int j = 0; j < 32; j++) wp[j] = w2[j];
    const float bh = bhh[row];

    __shared__ __align__(16) float hsh[HID];
    __shared__ float rsh[HID];
    __shared__ float zsh[HID];

    float hcur = 0.f;                    // live only in n-owner threads
    if (t < HID) hsh[t] = 0.f;
    __syncthreads();

    // 2-step lookahead input pipeline (owners only)
    const float* gxp = gx + row;
    float xv0 = 0.f, xv1 = 0.f;
    if (half == 0) {
        xv0 = __ldg(gxp);                        // step 0
        xv1 = __ldg(gxp + G3);                   // step 1
    }

    #pragma unroll 1
    for (int step = 0; step < SEQ; step++) {
        float xv = xv0;
        xv0 = xv1;
        if (half == 0)
            xv1 = (step + 2 < SEQ) ? __ldg(gxp + (size_t)(step + 2) * G3) : 0.f;

        // half-dot: 4 independent chains of 8 FFMA2 over 64 dims
        ull a0 = 0ull, a1 = 0ull, a2 = 0ull, a3 = 0ull;
        const ulonglong2* h2 = reinterpret_cast<const ulonglong2*>(hsh) + half * 16;
        #pragma unroll
        for (int j = 0; j < 8; j++) {
            ulonglong2 hva = h2[2 * j];
            ulonglong2 hvb = h2[2 * j + 1];
            asm("fma.rn.f32x2 %0, %1, %2, %0;" : "+l"(a0) : "l"(wp[4 * j]),     "l"(hva.x));
            asm("fma.rn.f32x2 %0, %1, %2, %0;" : "+l"(a1) : "l"(wp[4 * j + 1]), "l"(hva.y));
            asm("fma.rn.f32x2 %0, %1, %2, %0;" : "+l"(a2) : "l"(wp[4 * j + 2]), "l"(hvb.x));
            asm("fma.rn.f32x2 %0, %1, %2, %0;" : "+l"(a3) : "l"(wp[4 * j + 3]), "l"(hvb.y));
        }
        float l0, h0, l1, h1, l2, h2f, l3, h3;
        asm("mov.b64 {%0,%1}, %2;" : "=f"(l0), "=f"(h0) : "l"(a0));
        asm("mov.b64 {%0,%1}, %2;" : "=f"(l1), "=f"(h1) : "l"(a1));
        asm("mov.b64 {%0,%1}, %2;" : "=f"(l2), "=f"(h2f) : "l"(a2));
        asm("mov.b64 {%0,%1}, %2;" : "=f"(l3), "=f"(h3) : "l"(a3));
        float s = ((l0 + h0) + (l1 + h1)) + ((l2 + h2f) + (l3 + h3));
        s += __shfl_xor_sync(0xffffffffu, s, 1);   // combine halves
        float ghv = s + bh;

        // r/z owners: finish gate pre-barrier
        if (half == 0) {
            if (gate == 0)
                rsh[hid] = __fdividef(1.f, 1.f + __expf(-(xv + ghv)));
            else if (gate == 1)
                zsh[hid] = __fdividef(1.f, 1.f + __expf(-(xv + ghv)));
        }
        __syncthreads();

        // n owners: tanh + state update (h in registers)
        if (half == 0 && gate == 2) {
            float r = rsh[hid], z = zsh[hid];
            float narg = xv + r * ghv;
            float e2 = __expf(2.f * narg);
            float n = 1.f - __fdividef(2.f, e2 + 1.f);
            hcur = n + z * (hcur - n);
            hsh[hid] = hcur;
        }
        __syncthreads();
    }
    if (half == 0 && gate == 2) g_hcat[b * HID + hid] = hcur;
}

// ---------------------------------------------------------------------------
__global__ __launch_bounds__(256) void head_kernel(
    const float* __restrict__ fc1_w, const float* __restrict__ fc1_b,
    const float* __restrict__ fc2_w, const float* __restrict__ fc2_b,
    float* __restrict__ out)
{
    __shared__ float hs[256], ys[256], ls[3];
    const int t = threadIdx.x;
    hs[t] = g_hcat[t];
    __syncthreads();

    float acc = fc1_b[t];
    #pragma unroll 8
    for (int j = 0; j < 256; j++) acc += fc1_w[t * 256 + j] * hs[j];
    ys[t] = fmaxf(acc, 0.f);
    __syncthreads();

    if (t < 3) {
        float a = fc2_b[t];
        for (int j = 0; j < 256; j++) a += fc2_w[t * 256 + j] * ys[j];
        ls[t] = a;
    }
    __syncthreads();

    if (t == 0) {
        float m = fmaxf(ls[0], fmaxf(ls[1], ls[2]));
        float s = expf(ls[0] - m) + expf(ls[1] - m) + expf(ls[2] - m);
        float lse = m + logf(s);
        out[0] = ls[0] - lse; out[1] = ls[1] - lse; out[2] = ls[2] - lse;
    }
}

// ---------------------------------------------------------------------------
extern "C" void kernel_launch(void* const* d_in, const int* in_sizes, int n_in,
                              void* d_out, int out_size)
{
    (void)in_sizes; (void)n_in; (void)out_size;

    const float* x1     = (const float*)d_in[0];
    const float* x2     = (const float*)d_in[1];
    const float* q_w    = (const float*)d_in[2];
    const float* q_b    = (const float*)d_in[3];
    const float* k_w    = (const float*)d_in[4];
    const float* k_b    = (const float*)d_in[5];
    const float* v_w    = (const float*)d_in[6];
    const float* v_b    = (const float*)d_in[7];
    const float* aln_g  = (const float*)d_in[8];
    const float* aln_b  = (const float*)d_in[9];
    const float* w_w    = (const float*)d_in[10];
    const float* w_b    = (const float*)d_in[11];
    const float* mln_g  = (const float*)d_in[12];
    const float* mln_b  = (const float*)d_in[13];
    const float* g1_wih = (const float*)d_in[14];
    const float* g1_whh = (const float*)d_in[15];
    const float* g1_bih = (const float*)d_in[16];
    const float* g1_bhh = (const float*)d_in[17];
    const float* g2_wih = (const float*)d_in[18];
    const float* g2_whh = (const float*)d_in[19];
    const float* g2_bih = (const float*)d_in[20];
    const float* g2_bhh = (const float*)d_in[21];
    const float* fc1_w  = (const float*)d_in[22];
    const float* fc1_b  = (const float*)d_in[23];
    const float* fc2_w  = (const float*)d_in[24];
    const float* fc2_b  = (const float*)d_in[25];
    float* out = (float*)d_out;

    void *pv;
    cudaGetSymbolAddress(&pv, g_x);      float* p_x      = (float*)pv;
    cudaGetSymbolAddress(&pv, g_cur);    float* p_cur    = (float*)pv;
    cudaGetSymbolAddress(&pv, g_qkv);    float* p_qkv    = (float*)pv;
    cudaGetSymbolAddress(&pv, g_vt);     float* p_vt     = (float*)pv;
    cudaGetSymbolAddress(&pv, g_attn);   float* p_attn   = (float*)pv;
    cudaGetSymbolAddress(&pv, g_h);      float* p_h      = (float*)pv;
    cudaGetSymbolAddress(&pv, g_tmp);    float* p_tmp    = (float*)pv;
    cudaGetSymbolAddress(&pv, g_scores); float* p_scores = (float*)pv;
    cudaGetSymbolAddress(&pv, g_gx);     float* p_gx     = (float*)pv;
    cudaGetSymbolAddress(&pv, g_wqkv);   float* p_wqkv   = (float*)pv;
    cudaGetSymbolAddress(&pv, g_bqkv);   float* p_bqkv   = (float*)pv;
    cudaGetSymbolAddress(&pv, g_wih);    float* p_wih    = (float*)pv;
    cudaGetSymbolAddress(&pv, g_bih);    float* p_bih    = (float*)pv;

    const ll SV = (ll)SEQ * VECT;
    const ll S9 = (ll)SEQ * 3 * VECT;
    const ll SS = (ll)SEQ * SEQ;
    const int N9 = 3 * VECT;
    const float inv_scale = 0.05773502691896258f;   // 1/sqrt(300)

    const int SMEM_MMA = 3 * (2 * 128 * 36) * 4;    // 110592 B
    cudaFuncSetAttribute(mma_bt, cudaFuncAttributeMaxDynamicSharedMemorySize, SMEM_MMA);

    init_kernel<<<(2 * SEQ * VECT + 255) / 256, 256>>>(x1, x2);
    {
        int tot = 3 * VECT * VECT + 3 * VECT + 2 * G3 * VECT + 2 * G3;
        pack_kernel<<<(tot + 255) / 256, 256>>>(q_w, q_b, k_w, k_b, v_w, v_b,
                                                g1_wih, g1_bih, g2_wih, g2_bih);
    }

    dim3 gqkv(8, 32, 2);    // QKV proj: N=900 -> 8 tiles of 128
    dim3 gqk (32, 32, 2);   // QK^T: 4096x4096
    dim3 gav (3, 32, 2);    // A·V: N=300
    dim3 gw  (3, 32, 2);    // W proj
    dim3 gtr (10, 128, 2);  // V transpose

    for (int s = 0; s < NSTACK; s++) {
        mma_bt<<<gqkv, 256, SMEM_MMA>>>(p_cur, p_wqkv, p_qkv, SEQ, N9, VECT,
                                        VECT, VECT, N9, SV, 0, S9,
                                        p_bqkv, 0, 1.f);
        mma_bt<<<gqk, 256, SMEM_MMA>>>(p_qkv, p_qkv + VECT, p_scores, SEQ, SEQ, VECT,
                                       N9, N9, SEQ, S9, S9, SS,
                                       nullptr, 0, inv_scale);
        softmax_kernel<<<dim3(SEQ, 2), 256>>>(p_scores);

        transpose_kernel<<<gtr, 256>>>(p_qkv + 2 * VECT, p_vt, N9, S9, SV);
        mma_bt<<<gav, 256, SMEM_MMA>>>(p_scores, p_vt, p_attn, SEQ, VECT, SEQ,
                                       SEQ, SEQ, VECT, SS, SV, SV,
                                       nullptr, 0, 1.f);

        ln_add_kernel<<<dim3(SEQ / 4, 2), 128>>>(p_attn, p_cur, aln_g, aln_b, p_h);
        mma_bt<<<gw, 256, SMEM_MMA>>>(p_h, w_w, p_tmp, SEQ, VECT, VECT,
                                      VECT, VECT, VECT, SV, 0, SV,
                                      w_b, 0, 1.f);
        ln_add_kernel<<<dim3(SEQ / 4, 2), 128>>>(p_tmp, p_x, mln_g, mln_b, p_cur);
    }

    dim3 gg(3, 32, 2);
    mma_bt<<<gg, 256, SMEM_MMA>>>(p_cur, p_wih, p_gx, SEQ, G3, VECT,
                                  VECT, VECT, G3, SV, (ll)G3 * VECT, (ll)SEQ * G3,
                                  p_bih, G3, 1.f);
    gru_kernel<<<2, 768>>>(g1_whh, g1_bhh, g2_whh, g2_bhh);
    head_kernel<<<1, 256>>>(fc1_w, fc1_b, fc2_w, fc2_b, out);
}

// round 12
// speedup vs baseline: 1.6311x; 1.6311x over previous
#include <cuda_runtime.h>
#include <cstdint>

#define SEQ   4096
#define VECT  300
#define HID   128
#define G3    384
#define NSTACK 3

typedef unsigned long long ull;
typedef long long ll;

// ---------------------------------------------------------------------------
// Scratch (static device globals — allocation-free)
// ---------------------------------------------------------------------------
__device__ float g_x    [2 * SEQ * VECT];
__device__ float g_cur  [2 * SEQ * VECT];
__device__ float g_qkv  [2ll * SEQ * 3 * VECT];   // packed [seq][row][900]: Q|K|V
__device__ float g_vt   [2 * SEQ * VECT];         // V^T per seq: [VECT][SEQ]
__device__ float g_attn [2 * SEQ * VECT];
__device__ float g_h    [2 * SEQ * VECT];
__device__ float g_tmp  [2 * SEQ * VECT];
__device__ float g_scores[2ll * SEQ * SEQ];
__device__ float2 g_stats[2 * SEQ];               // per-row (max, 1/sum)
__device__ float g_gx   [2 * SEQ * G3];
__device__ float g_hcat [2 * HID];
// packed weights
__device__ float g_wqkv [3 * VECT * VECT];
__device__ float g_bqkv [3 * VECT];
__device__ float g_wih  [2 * G3 * VECT];
__device__ float g_bih  [2 * G3];

// ---------------------------------------------------------------------------
__global__ void init_kernel(const float* __restrict__ x1, const float* __restrict__ x2)
{
    int i = blockIdx.x * blockDim.x + threadIdx.x;
    const int n = SEQ * VECT;
    if (i < n) {
        float v = x1[i];
        g_x[i] = v; g_cur[i] = v;
    } else if (i < 2 * n) {
        float v = x2[i - n];
        g_x[i] = v; g_cur[i] = v;
    }
}

// ---------------------------------------------------------------------------
__global__ void pack_kernel(
    const float* __restrict__ qw, const float* __restrict__ qb,
    const float* __restrict__ kw, const float* __restrict__ kb,
    const float* __restrict__ vw, const float* __restrict__ vb,
    const float* __restrict__ w1, const float* __restrict__ b1,
    const float* __restrict__ w2, const float* __restrict__ b2)
{
    const int N1 = 3 * VECT * VECT;
    const int N2 = 3 * VECT;
    const int N3 = 2 * G3 * VECT;
    const int N4 = 2 * G3;
    int i = blockIdx.x * blockDim.x + threadIdx.x;
    if (i < N1) {
        int row = i / VECT, col = i % VECT;
        float v;
        if (row < VECT)            v = qw[row * VECT + col];
        else if (row < 2 * VECT)   v = kw[(row - VECT) * VECT + col];
        else                       v = vw[(row - 2 * VECT) * VECT + col];
        g_wqkv[i] = v;
    } else if (i < N1 + N2) {
        int r = i - N1;
        g_bqkv[r] = (r < VECT) ? qb[r] : (r < 2 * VECT) ? kb[r - VECT] : vb[r - 2 * VECT];
    } else if (i < N1 + N2 + N3) {
        int j = i - N1 - N2;
        g_wih[j] = (j < G3 * VECT) ? w1[j] : w2[j - G3 * VECT];
    } else if (i < N1 + N2 + N3 + N4) {
        int j = i - N1 - N2 - N3;
        g_bih[j] = (j < G3) ? b1[j] : b2[j - G3];
    }
}

// ---------------------------------------------------------------------------
// Transpose: dst[c][r] = src[r][c]. src [SEQ, VECT] (ld=lds), dst [VECT][SEQ].
// ---------------------------------------------------------------------------
__global__ __launch_bounds__(256) void transpose_kernel(
    const float* __restrict__ src, float* __restrict__ dst,
    int lds, ll sSrc, ll sDst)
{
    __shared__ float t[32][33];
    src += (ll)blockIdx.z * sSrc;
    dst += (ll)blockIdx.z * sDst;
    const int r0 = blockIdx.y * 32, c0 = blockIdx.x * 32;
    const int x = threadIdx.x & 31, y = threadIdx.x >> 5;

    #pragma unroll
    for (int i = 0; i < 4; i++) {
        int col = c0 + x;
        if (col < VECT) t[y + 8 * i][x] = src[(size_t)(r0 + y + 8 * i) * lds + col];
    }
    __syncthreads();
    #pragma unroll
    for (int i = 0; i < 4; i++) {
        int c = c0 + y + 8 * i;
        if (c < VECT) dst[(size_t)c * SEQ + r0 + x] = t[x][y + 8 * i];
    }
}

// ---------------------------------------------------------------------------
// MMA helpers
// ---------------------------------------------------------------------------
__device__ __forceinline__ unsigned smem_u32(const void* p)
{
    return (unsigned)__cvta_generic_to_shared(p);
}
__device__ __forceinline__ void cp_async16(unsigned dst, const float* src, bool valid)
{
    int sz = valid ? 16 : 0;   // src-size 0 -> zero-fill 16B
    asm volatile("cp.async.cg.shared.global [%0], [%1], 16, %2;\n"
                 :: "r"(dst), "l"(src), "r"(sz));
}
__device__ __forceinline__ void ldsm_x4(uint32_t* r, unsigned addr)
{
    asm volatile("ldmatrix.sync.aligned.m8n8.x4.shared.b16 {%0,%1,%2,%3}, [%4];"
                 : "=r"(r[0]), "=r"(r[1]), "=r"(r[2]), "=r"(r[3]) : "r"(addr));
}
__device__ __forceinline__ void mma8(float* c, const uint32_t* a, const uint32_t* b)
{
    asm volatile(
        "mma.sync.aligned.m16n8k8.row.col.f32.tf32.tf32.f32 "
        "{%0,%1,%2,%3}, {%4,%5,%6,%7}, {%8,%9}, {%0,%1,%2,%3};"
        : "+f"(c[0]), "+f"(c[1]), "+f"(c[2]), "+f"(c[3])
        : "r"(a[0]), "r"(a[1]), "r"(a[2]), "r"(a[3]), "r"(b[0]), "r"(b[1]));
}

// ---------------------------------------------------------------------------
// TF32 GEMM: C[M,N] = alpha*A[M,K]*B[N,K]^T (+bias), 128x128x32, 3-stage.
// M % 128 == 0 assumed.
// SMODE: A elements are raw scores; apply exp(a - row_max) in smem before
// the MMA and scale the output row by 1/row_sum in the epilogue (fused
// softmax for the A·V GEMM). stats[row] = (max, 1/sum), per-z stride SEQ.
// ---------------------------------------------------------------------------
template<bool SMODE>
__global__ __launch_bounds__(256, 2) void mma_bt(
    const float* __restrict__ A, const float* __restrict__ B, float* __restrict__ C,
    int M, int N, int K, int lda, int ldb, int ldc,
    ll sAb, ll sBb, ll sCb,
    const float* __restrict__ bias, ll sBiasb, float alpha,
    const float2* __restrict__ stats)
{
    constexpr int BM = 128, BN = 128, BK = 32, AP = 36;
    constexpr int ASZ = BM * AP;
    constexpr int STG = 2 * ASZ;

    extern __shared__ float sm[];

    A += (ll)blockIdx.z * sAb;
    B += (ll)blockIdx.z * sBb;
    C += (ll)blockIdx.z * sCb;
    if (bias) bias += (ll)blockIdx.z * sBiasb;
    const float2* st = SMODE ? stats + (ll)blockIdx.z * SEQ : nullptr;

    const int m0 = blockIdx.y * BM, n0 = blockIdx.x * BN;
    const int tid = threadIdx.x, lane = tid & 31, warp = tid >> 5;
    const int g = lane >> 2, tg = lane & 3;
    const int wm = (warp & 1) * 64, wn = (warp >> 1) * 32;

    const int lm   = lane >> 3;
    const int lrow = (lm & 1) * 8 + (lane & 7);
    const int lcol = (lm >> 1) * 4;

    // per-thread A rows are fixed across k-iters: preload row maxes
    float rowm[4];
    if (SMODE) {
        #pragma unroll
        for (int i = 0; i < 4; i++)
            rowm[i] = st[m0 + ((tid + i * 256) >> 3)].x;
    }

    float acc[4][4][4] = {};
    const int nk = (K + BK - 1) / BK;

    auto load_stage = [&](int s, int k0) {
        unsigned base = smem_u32(sm + s * STG);
        #pragma unroll
        for (int i = 0; i < 4; i++) {
            int idx = tid + i * 256;
            int r = idx >> 3, c = (idx & 7) * 4;
            cp_async16(base + (unsigned)(r * AP + c) * 4,
                       A + (size_t)(m0 + r) * lda + k0 + c, (k0 + c < K));
        }
        #pragma unroll
        for (int i = 0; i < 4; i++) {
            int idx = tid + i * 256;
            int r = idx >> 3, c = (idx & 7) * 4;
            bool v = (n0 + r < N) && (k0 + c < K);
            cp_async16(base + (unsigned)(ASZ + r * AP + c) * 4,
                       B + (size_t)(n0 + r) * ldb + k0 + c, v);
        }
        asm volatile("cp.async.commit_group;");
    };

    load_stage(0, 0);
    if (nk > 1) load_stage(1, BK);

    for (int kt = 0; kt < nk; kt++) {
        int s = kt % 3;
        if (kt + 1 < nk) asm volatile("cp.async.wait_group 1;");
        else             asm volatile("cp.async.wait_group 0;");
        __syncthreads();

        if (kt + 2 < nk) load_stage((kt + 2) % 3, (kt + 2) * BK);

        if (SMODE) {
            // exp-transform this stage's A tile in smem (overlaps cp.async)
            float* As = sm + s * STG;
            #pragma unroll
            for (int i = 0; i < 4; i++) {
                int idx = tid + i * 256;
                int r = idx >> 3, c = (idx & 7) * 4;
                float4* p = reinterpret_cast<float4*>(As + r * AP + c);
                float4 v = *p;
                v.x = __expf(v.x - rowm[i]);
                v.y = __expf(v.y - rowm[i]);
                v.z = __expf(v.z - rowm[i]);
                v.w = __expf(v.w - rowm[i]);
                *p = v;
            }
            __syncthreads();
        }

        unsigned aBase = smem_u32(sm + s * STG)
                       + (unsigned)((wm + lrow) * AP + lcol) * 4;
        unsigned bBase = smem_u32(sm + s * STG + ASZ)
                       + (unsigned)((wn + lrow) * AP + lcol) * 4;

        #pragma unroll
        for (int kk = 0; kk < BK; kk += 8) {
            uint32_t ar[4][4];
            #pragma unroll
            for (int mt = 0; mt < 4; mt++)
                ldsm_x4(ar[mt], aBase + (unsigned)(mt * 16 * AP + kk) * 4);
            uint32_t brq[2][4];
            #pragma unroll
            for (int nh = 0; nh < 2; nh++)
                ldsm_x4(brq[nh], bBase + (unsigned)(nh * 16 * AP + kk) * 4);

            #pragma unroll
            for (int mt = 0; mt < 4; mt++) {
                #pragma unroll
                for (int nt = 0; nt < 4; nt++) {
                    uint32_t bb[2] = { brq[nt >> 1][nt & 1], brq[nt >> 1][(nt & 1) + 2] };
                    mma8(acc[mt][nt], ar[mt], bb);
                }
            }
        }
    }

    #pragma unroll
    for (int mt = 0; mt < 4; mt++) {
        #pragma unroll
        for (int nt = 0; nt < 4; nt++) {
            int row0 = m0 + wm + mt * 16 + g;
            int col  = n0 + wn + nt * 8 + 2 * tg;
            float s0 = alpha, s1 = alpha;
            if (SMODE) {
                s0 = st[row0].y;
                s1 = st[row0 + 8].y;
            }
            if (col + 1 < N) {
                float b0 = bias ? bias[col]     : 0.f;
                float b1 = bias ? bias[col + 1] : 0.f;
                float2 v0 = make_float2(s0 * acc[mt][nt][0] + b0,
                                        s0 * acc[mt][nt][1] + b1);
                float2 v1 = make_float2(s1 * acc[mt][nt][2] + b0,
                                        s1 * acc[mt][nt][3] + b1);
                *reinterpret_cast<float2*>(C + (size_t)row0 * ldc + col) = v0;
                *reinterpret_cast<float2*>(C + (size_t)(row0 + 8) * ldc + col) = v1;
            } else if (col < N) {
                float b0 = bias ? bias[col] : 0.f;
                C[(size_t)row0 * ldc + col]       = s0 * acc[mt][nt][0] + b0;
                C[(size_t)(row0 + 8) * ldc + col] = s1 * acc[mt][nt][2] + b0;
            }
        }
    }
}

// ---------------------------------------------------------------------------
__device__ __forceinline__ float warp_max(float v) {
    #pragma unroll
    for (int o = 16; o > 0; o >>= 1) v = fmaxf(v, __shfl_xor_sync(0xffffffffu, v, o));
    return v;
}
__device__ __forceinline__ float warp_sum(float v) {
    #pragma unroll
    for (int o = 16; o > 0; o >>= 1) v += __shfl_xor_sync(0xffffffffu, v, o);
    return v;
}

// ---------------------------------------------------------------------------
// Row stats: per score-row (max, 1/sum_exp). Read-only pass over scores.
// grid (SEQ, 2), 256 threads.
// ---------------------------------------------------------------------------
__global__ __launch_bounds__(256) void row_stats_kernel(
    const float* __restrict__ Sm, float2* __restrict__ stats)
{
    size_t off = ((size_t)blockIdx.y * SEQ + blockIdx.x) * SEQ;
    const float4* row4 = reinterpret_cast<const float4*>(Sm + off);
    const int t = threadIdx.x;
    const int lane = t & 31, wid = t >> 5;

    float4 v[4];
    #pragma unroll
    for (int i = 0; i < 4; i++) v[i] = row4[t + 256 * i];

    float m = -3.4e38f;
    #pragma unroll
    for (int i = 0; i < 4; i++)
        m = fmaxf(m, fmaxf(fmaxf(v[i].x, v[i].y), fmaxf(v[i].z, v[i].w)));

    __shared__ float red[8];
    m = warp_max(m);
    if (lane == 0) red[wid] = m;
    __syncthreads();
    float bm = red[0];
    #pragma unroll
    for (int k = 1; k < 8; k++) bm = fmaxf(bm, red[k]);

    float s = 0.f;
    #pragma unroll
    for (int i = 0; i < 4; i++) {
        s += __expf(v[i].x - bm) + __expf(v[i].y - bm)
           + __expf(v[i].z - bm) + __expf(v[i].w - bm);
    }
    s = warp_sum(s);
    __syncthreads();
    if (lane == 0) red[wid] = s;
    __syncthreads();
    float bs = 0.f;
    #pragma unroll
    for (int k = 0; k < 8; k++) bs += red[k];

    if (t == 0)
        stats[blockIdx.y * SEQ + blockIdx.x] = make_float2(bm, 1.f / bs);
}

// ---------------------------------------------------------------------------
__global__ __launch_bounds__(128) void ln_add_kernel(
    const float* __restrict__ s1, const float* __restrict__ s2,
    const float* __restrict__ g, const float* __restrict__ b,
    float* __restrict__ dst)
{
    const int wid = threadIdx.x >> 5, lane = threadIdx.x & 31;
    const int row = blockIdx.x * 4 + wid;
    const size_t base = ((size_t)blockIdx.y * SEQ + row) * VECT;

    float v[10];
    float s = 0.f;
    #pragma unroll
    for (int i = 0; i < 10; i++) {
        int j = lane + 32 * i;
        float x = 0.f;
        if (j < VECT) x = s1[base + j] + s2[base + j];
        v[i] = x; s += x;
    }
    s = warp_sum(s);
    float mean = s * (1.f / VECT);

    float var = 0.f;
    #pragma unroll
    for (int i = 0; i < 10; i++) {
        int j = lane + 32 * i;
        if (j < VECT) { float d = v[i] - mean; var += d * d; }
    }
    var = warp_sum(var) * (1.f / VECT);
    float inv = rsqrtf(var + 1e-5f);

    #pragma unroll
    for (int i = 0; i < 10; i++) {
        int j = lane + 32 * i;
        if (j < VECT) dst[base + j] = g[j] * (v[i] - mean) * inv + b[j];
    }
}

// ---------------------------------------------------------------------------
// GRU recurrence (round-9 proven version). 2 blocks, 384 threads.
// Gate-parallel: thread t owns w_hh row t (gate = t>>7). r/z threads compute
// their sigmoid pre-barrier; n-threads own h in registers. Early __ldg of gx.
// ---------------------------------------------------------------------------
__global__ __launch_bounds__(384, 1) void gru_kernel(
    const float* __restrict__ whh1, const float* __restrict__ bhh1,
    const float* __restrict__ whh2, const float* __restrict__ bhh2)
{
    const int b = blockIdx.x;
    const float* whh = b ? whh2 : whh1;
    const float* bhh = b ? bhh2 : bhh1;
    const float* gx  = g_gx + (size_t)b * SEQ * G3;
    const int t = threadIdx.x;
    const int gate = t >> 7;         // 0=r, 1=z, 2=n
    const int hid  = t & 127;

    ull wp[64];
    const ull* w2 = reinterpret_cast<const ull*>(whh + t * HID);
    #pragma unroll
    for (int j = 0; j < 64; j++) wp[j] = w2[j];
    const float bh = bhh[t];

    __shared__ __align__(16) float hsh[HID];
    __shared__ float rsh[HID];
    __shared__ float zsh[HID];

    float hcur = 0.f;                 // live only in n-threads
    if (t < HID) hsh[t] = 0.f;
    __syncthreads();

    const float* gxp = gx + t;

    #pragma unroll 1
    for (int step = 0; step < SEQ; step++) {
        // early input load — consumed ~384 cycles later
        float xv = __ldg(gxp + (size_t)step * G3);

        // gh_t = dot(whh_t, h) + bhh_t  (4 independent FFMA2 chains)
        ull a0 = 0ull, a1 = 0ull, a2 = 0ull, a3 = 0ull;
        const ulonglong2* h2 = reinterpret_cast<const ulonglong2*>(hsh);
        #pragma unroll
        for (int j = 0; j < 16; j++) {
            ulonglong2 hva = h2[2 * j];
            ulonglong2 hvb = h2[2 * j + 1];
            asm("fma.rn.f32x2 %0, %1, %2, %0;" : "+l"(a0) : "l"(wp[4 * j]),     "l"(hva.x));
            asm("fma.rn.f32x2 %0, %1, %2, %0;" : "+l"(a1) : "l"(wp[4 * j + 1]), "l"(hva.y));
            asm("fma.rn.f32x2 %0, %1, %2, %0;" : "+l"(a2) : "l"(wp[4 * j + 2]), "l"(hvb.x));
            asm("fma.rn.f32x2 %0, %1, %2, %0;" : "+l"(a3) : "l"(wp[4 * j + 3]), "l"(hvb.y));
        }
        float l0, h0, l1, h1, l2, h2f, l3, h3;
        asm("mov.b64 {%0,%1}, %2;" : "=f"(l0), "=f"(h0) : "l"(a0));
        asm("mov.b64 {%0,%1}, %2;" : "=f"(l1), "=f"(h1) : "l"(a1));
        asm("mov.b64 {%0,%1}, %2;" : "=f"(l2), "=f"(h2f) : "l"(a2));
        asm("mov.b64 {%0,%1}, %2;" : "=f"(l3), "=f"(h3) : "l"(a3));
        float ghv = ((l0 + h0) + (l1 + h1)) + ((l2 + h2f) + (l3 + h3)) + bh;

        // r/z: finish gate pre-barrier (overlaps other warps' FMA issue)
        if (gate == 0) {
            rsh[hid] = __fdividef(1.f, 1.f + __expf(-(xv + ghv)));
        } else if (gate == 1) {
            zsh[hid] = __fdividef(1.f, 1.f + __expf(-(xv + ghv)));
        }
        __syncthreads();

        // n-threads: tanh + state update (h lives in their registers)
        if (gate == 2) {
            float r = rsh[hid], z = zsh[hid];
            float narg = xv + r * ghv;
            float e2 = __expf(2.f * narg);
            float n = 1.f - __fdividef(2.f, e2 + 1.f);
            hcur = n + z * (hcur - n);
            hsh[hid] = hcur;
        }
        __syncthreads();
    }
    if (gate == 2) g_hcat[b * HID + hid] = hcur;
}

// ---------------------------------------------------------------------------
__global__ __launch_bounds__(256) void head_kernel(
    const float* __restrict__ fc1_w, const float* __restrict__ fc1_b,
    const float* __restrict__ fc2_w, const float* __restrict__ fc2_b,
    float* __restrict__ out)
{
    __shared__ float hs[256], ys[256], ls[3];
    const int t = threadIdx.x;
    hs[t] = g_hcat[t];
    __syncthreads();

    float acc = fc1_b[t];
    #pragma unroll 8
    for (int j = 0; j < 256; j++) acc += fc1_w[t * 256 + j] * hs[j];
    ys[t] = fmaxf(acc, 0.f);
    __syncthreads();

    if (t < 3) {
        float a = fc2_b[t];
        for (int j = 0; j < 256; j++) a += fc2_w[t * 256 + j] * ys[j];
        ls[t] = a;
    }
    __syncthreads();

    if (t == 0) {
        float m = fmaxf(ls[0], fmaxf(ls[1], ls[2]));
        float s = expf(ls[0] - m) + expf(ls[1] - m) + expf(ls[2] - m);
        float lse = m + logf(s);
        out[0] = ls[0] - lse; out[1] = ls[1] - lse; out[2] = ls[2] - lse;
    }
}

// ---------------------------------------------------------------------------
extern "C" void kernel_launch(void* const* d_in, const int* in_sizes, int n_in,
                              void* d_out, int out_size)
{
    (void)in_sizes; (void)n_in; (void)out_size;

    const float* x1     = (const float*)d_in[0];
    const float* x2     = (const float*)d_in[1];
    const float* q_w    = (const float*)d_in[2];
    const float* q_b    = (const float*)d_in[3];
    const float* k_w    = (const float*)d_in[4];
    const float* k_b    = (const float*)d_in[5];
    const float* v_w    = (const float*)d_in[6];
    const float* v_b    = (const float*)d_in[7];
    const float* aln_g  = (const float*)d_in[8];
    const float* aln_b  = (const float*)d_in[9];
    const float* w_w    = (const float*)d_in[10];
    const float* w_b    = (const float*)d_in[11];
    const float* mln_g  = (const float*)d_in[12];
    const float* mln_b  = (const float*)d_in[13];
    const float* g1_wih = (const float*)d_in[14];
    const float* g1_whh = (const float*)d_in[15];
    const float* g1_bih = (const float*)d_in[16];
    const float* g1_bhh = (const float*)d_in[17];
    const float* g2_wih = (const float*)d_in[18];
    const float* g2_whh = (const float*)d_in[19];
    const float* g2_bih = (const float*)d_in[20];
    const float* g2_bhh = (const float*)d_in[21];
    const float* fc1_w  = (const float*)d_in[22];
    const float* fc1_b  = (const float*)d_in[23];
    const float* fc2_w  = (const float*)d_in[24];
    const float* fc2_b  = (const float*)d_in[25];
    float* out = (float*)d_out;

    void *pv;
    cudaGetSymbolAddress(&pv, g_x);      float* p_x      = (float*)pv;
    cudaGetSymbolAddress(&pv, g_cur);    float* p_cur    = (float*)pv;
    cudaGetSymbolAddress(&pv, g_qkv);    float* p_qkv    = (float*)pv;
    cudaGetSymbolAddress(&pv, g_vt);     float* p_vt     = (float*)pv;
    cudaGetSymbolAddress(&pv, g_attn);   float* p_attn   = (float*)pv;
    cudaGetSymbolAddress(&pv, g_h);      float* p_h      = (float*)pv;
    cudaGetSymbolAddress(&pv, g_tmp);    float* p_tmp    = (float*)pv;
    cudaGetSymbolAddress(&pv, g_scores); float* p_scores = (float*)pv;
    cudaGetSymbolAddress(&pv, g_stats);  float2* p_stats = (float2*)pv;
    cudaGetSymbolAddress(&pv, g_gx);     float* p_gx     = (float*)pv;
    cudaGetSymbolAddress(&pv, g_wqkv);   float* p_wqkv   = (float*)pv;
    cudaGetSymbolAddress(&pv, g_bqkv);   float* p_bqkv   = (float*)pv;
    cudaGetSymbolAddress(&pv, g_wih);    float* p_wih    = (float*)pv;
    cudaGetSymbolAddress(&pv, g_bih);    float* p_bih    = (float*)pv;

    const ll SV = (ll)SEQ * VECT;
    const ll S9 = (ll)SEQ * 3 * VECT;
    const ll SS = (ll)SEQ * SEQ;
    const int N9 = 3 * VECT;
    const float inv_scale = 0.05773502691896258f;   // 1/sqrt(300)

    const int SMEM_MMA = 3 * (2 * 128 * 36) * 4;    // 110592 B
    cudaFuncSetAttribute(mma_bt<false>, cudaFuncAttributeMaxDynamicSharedMemorySize, SMEM_MMA);
    cudaFuncSetAttribute(mma_bt<true>,  cudaFuncAttributeMaxDynamicSharedMemorySize, SMEM_MMA);

    init_kernel<<<(2 * SEQ * VECT + 255) / 256, 256>>>(x1, x2);
    {
        int tot = 3 * VECT * VECT + 3 * VECT + 2 * G3 * VECT + 2 * G3;
        pack_kernel<<<(tot + 255) / 256, 256>>>(q_w, q_b, k_w, k_b, v_w, v_b,
                                                g1_wih, g1_bih, g2_wih, g2_bih);
    }

    dim3 gqkv(8, 32, 2);    // QKV proj: N=900 -> 8 tiles of 128
    dim3 gqk (32, 32, 2);   // QK^T: 4096x4096
    dim3 gav (3, 32, 2);    // A·V: N=300
    dim3 gw  (3, 32, 2);    // W proj
    dim3 gtr (10, 128, 2);  // V transpose

    for (int s = 0; s < NSTACK; s++) {
        mma_bt<false><<<gqkv, 256, SMEM_MMA>>>(p_cur, p_wqkv, p_qkv, SEQ, N9, VECT,
                                               VECT, VECT, N9, SV, 0, S9,
                                               p_bqkv, 0, 1.f, nullptr);
        mma_bt<false><<<gqk, 256, SMEM_MMA>>>(p_qkv, p_qkv + VECT, p_scores, SEQ, SEQ, VECT,
                                              N9, N9, SEQ, S9, S9, SS,
                                              nullptr, 0, inv_scale, nullptr);
        row_stats_kernel<<<dim3(SEQ, 2), 256>>>(p_scores, p_stats);

        transpose_kernel<<<gtr, 256>>>(p_qkv + 2 * VECT, p_vt, N9, S9, SV);
        // fused softmax + A·V: exp in smem, 1/sum in epilogue
        mma_bt<true><<<gav, 256, SMEM_MMA>>>(p_scores, p_vt, p_attn, SEQ, VECT, SEQ,
                                             SEQ, SEQ, VECT, SS, SV, SV,
                                             nullptr, 0, 1.f, p_stats);

        ln_add_kernel<<<dim3(SEQ / 4, 2), 128>>>(p_attn, p_cur, aln_g, aln_b, p_h);
        mma_bt<false><<<gw, 256, SMEM_MMA>>>(p_h, w_w, p_tmp, SEQ, VECT, VECT,
                                             VECT, VECT, VECT, SV, 0, SV,
                                             w_b, 0, 1.f, nullptr);
        ln_add_kernel<<<dim3(SEQ / 4, 2), 128>>>(p_tmp, p_x, mln_g, mln_b, p_cur);
    }

    dim3 gg(3, 32, 2);
    mma_bt<false><<<gg, 256, SMEM_MMA>>>(p_cur, p_wih, p_gx, SEQ, G3, VECT,
                                         VECT, VECT, G3, SV, (ll)G3 * VECT, (ll)SEQ * G3,
                                         p_bih, G3, 1.f, nullptr);
    gru_kernel<<<2, 384>>>(g1_whh, g1_bhh, g2_whh, g2_bhh);
    head_kernel<<<1, 256>>>(fc1_w, fc1_b, fc2_w, fc2_b, out);
}

// round 13
// speedup vs baseline: 2.5646x; 1.5723x over previous
#include <cuda_runtime.h>
#include <cstdint>

#define SEQ   4096
#define VECT  300
#define HID   128
#define G3    384
#define NSTACK 3

typedef unsigned long long ull;
typedef long long ll;

// ---------------------------------------------------------------------------
// Scratch (static device globals — allocation-free)
// ---------------------------------------------------------------------------
__device__ float g_x    [2 * SEQ * VECT];
__device__ float g_cur  [2 * SEQ * VECT];
__device__ float g_qkv  [2ll * SEQ * 3 * VECT];   // packed [seq][row][900]: Q|K|V
__device__ float g_vt   [2 * SEQ * VECT];         // V^T per seq: [VECT][SEQ]
__device__ float g_attn [2 * SEQ * VECT];
__device__ float g_h    [2 * SEQ * VECT];
__device__ float g_tmp  [2 * SEQ * VECT];
__device__ float g_scores[2ll * SEQ * SEQ];
__device__ float2 g_stats[2 * SEQ];               // per-row (max, 1/sum)
__device__ float g_gx   [2 * SEQ * G3];
__device__ float g_hcat [2 * HID];
// packed weights
__device__ float g_wqkv [3 * VECT * VECT];
__device__ float g_bqkv [3 * VECT];
__device__ float g_wih  [2 * G3 * VECT];
__device__ float g_bih  [2 * G3];

// ---------------------------------------------------------------------------
__global__ void init_kernel(const float* __restrict__ x1, const float* __restrict__ x2)
{
    int i = blockIdx.x * blockDim.x + threadIdx.x;
    const int n = SEQ * VECT;
    if (i < n) {
        float v = x1[i];
        g_x[i] = v; g_cur[i] = v;
    } else if (i < 2 * n) {
        float v = x2[i - n];
        g_x[i] = v; g_cur[i] = v;
    }
}

// ---------------------------------------------------------------------------
__global__ void pack_kernel(
    const float* __restrict__ qw, const float* __restrict__ qb,
    const float* __restrict__ kw, const float* __restrict__ kb,
    const float* __restrict__ vw, const float* __restrict__ vb,
    const float* __restrict__ w1, const float* __restrict__ b1,
    const float* __restrict__ w2, const float* __restrict__ b2)
{
    const int N1 = 3 * VECT * VECT;
    const int N2 = 3 * VECT;
    const int N3 = 2 * G3 * VECT;
    const int N4 = 2 * G3;
    int i = blockIdx.x * blockDim.x + threadIdx.x;
    if (i < N1) {
        int row = i / VECT, col = i % VECT;
        float v;
        if (row < VECT)            v = qw[row * VECT + col];
        else if (row < 2 * VECT)   v = kw[(row - VECT) * VECT + col];
        else                       v = vw[(row - 2 * VECT) * VECT + col];
        g_wqkv[i] = v;
    } else if (i < N1 + N2) {
        int r = i - N1;
        g_bqkv[r] = (r < VECT) ? qb[r] : (r < 2 * VECT) ? kb[r - VECT] : vb[r - 2 * VECT];
    } else if (i < N1 + N2 + N3) {
        int j = i - N1 - N2;
        g_wih[j] = (j < G3 * VECT) ? w1[j] : w2[j - G3 * VECT];
    } else if (i < N1 + N2 + N3 + N4) {
        int j = i - N1 - N2 - N3;
        g_bih[j] = (j < G3) ? b1[j] : b2[j - G3];
    }
}

// ---------------------------------------------------------------------------
// Transpose: dst[c][r] = src[r][c]. src [SEQ, VECT] (ld=lds), dst [VECT][SEQ].
// ---------------------------------------------------------------------------
__global__ __launch_bounds__(256) void transpose_kernel(
    const float* __restrict__ src, float* __restrict__ dst,
    int lds, ll sSrc, ll sDst)
{
    __shared__ float t[32][33];
    src += (ll)blockIdx.z * sSrc;
    dst += (ll)blockIdx.z * sDst;
    const int r0 = blockIdx.y * 32, c0 = blockIdx.x * 32;
    const int x = threadIdx.x & 31, y = threadIdx.x >> 5;

    #pragma unroll
    for (int i = 0; i < 4; i++) {
        int col = c0 + x;
        if (col < VECT) t[y + 8 * i][x] = src[(size_t)(r0 + y + 8 * i) * lds + col];
    }
    __syncthreads();
    #pragma unroll
    for (int i = 0; i < 4; i++) {
        int c = c0 + y + 8 * i;
        if (c < VECT) dst[(size_t)c * SEQ + r0 + x] = t[x][y + 8 * i];
    }
}

// ---------------------------------------------------------------------------
// MMA helpers
// ---------------------------------------------------------------------------
__device__ __forceinline__ unsigned smem_u32(const void* p)
{
    return (unsigned)__cvta_generic_to_shared(p);
}
__device__ __forceinline__ void cp_async16(unsigned dst, const float* src, bool valid)
{
    int sz = valid ? 16 : 0;   // src-size 0 -> zero-fill 16B
    asm volatile("cp.async.cg.shared.global [%0], [%1], 16, %2;\n"
                 :: "r"(dst), "l"(src), "r"(sz));
}
__device__ __forceinline__ void ldsm_x4(uint32_t* r, unsigned addr)
{
    asm volatile("ldmatrix.sync.aligned.m8n8.x4.shared.b16 {%0,%1,%2,%3}, [%4];"
                 : "=r"(r[0]), "=r"(r[1]), "=r"(r[2]), "=r"(r[3]) : "r"(addr));
}
__device__ __forceinline__ void mma8(float* c, const uint32_t* a, const uint32_t* b)
{
    asm volatile(
        "mma.sync.aligned.m16n8k8.row.col.f32.tf32.tf32.f32 "
        "{%0,%1,%2,%3}, {%4,%5,%6,%7}, {%8,%9}, {%0,%1,%2,%3};"
        : "+f"(c[0]), "+f"(c[1]), "+f"(c[2]), "+f"(c[3])
        : "r"(a[0]), "r"(a[1]), "r"(a[2]), "r"(a[3]), "r"(b[0]), "r"(b[1]));
}

// ---------------------------------------------------------------------------
// TF32 GEMM: C[M,N] = alpha*A[M,K]*B[N,K]^T (+bias), 128x128x32, 3-stage.
// M % 128 == 0 assumed.
// SMODE: A elements are raw scores; apply exp(a - row_max) in smem before
// the MMA and scale the output row by 1/row_sum in the epilogue (fused
// softmax for the A·V GEMM). stats[row] = (max, 1/sum), per-z stride SEQ.
// ---------------------------------------------------------------------------
template<bool SMODE>
__global__ __launch_bounds__(256, 2) void mma_bt(
    const float* __restrict__ A, const float* __restrict__ B, float* __restrict__ C,
    int M, int N, int K, int lda, int ldb, int ldc,
    ll sAb, ll sBb, ll sCb,
    const float* __restrict__ bias, ll sBiasb, float alpha,
    const float2* __restrict__ stats)
{
    constexpr int BM = 128, BN = 128, BK = 32, AP = 36;
    constexpr int ASZ = BM * AP;
    constexpr int STG = 2 * ASZ;

    extern __shared__ float sm[];

    A += (ll)blockIdx.z * sAb;
    B += (ll)blockIdx.z * sBb;
    C += (ll)blockIdx.z * sCb;
    if (bias) bias += (ll)blockIdx.z * sBiasb;
    const float2* st = SMODE ? stats + (ll)blockIdx.z * SEQ : nullptr;

    const int m0 = blockIdx.y * BM, n0 = blockIdx.x * BN;
    const int tid = threadIdx.x, lane = tid & 31, warp = tid >> 5;
    const int g = lane >> 2, tg = lane & 3;
    const int wm = (warp & 1) * 64, wn = (warp >> 1) * 32;

    const int lm   = lane >> 3;
    const int lrow = (lm & 1) * 8 + (lane & 7);
    const int lcol = (lm >> 1) * 4;

    // per-thread A rows are fixed across k-iters: preload row maxes
    float rowm[4];
    if (SMODE) {
        #pragma unroll
        for (int i = 0; i < 4; i++)
            rowm[i] = st[m0 + ((tid + i * 256) >> 3)].x;
    }

    float acc[4][4][4] = {};
    const int nk = (K + BK - 1) / BK;

    auto load_stage = [&](int s, int k0) {
        unsigned base = smem_u32(sm + s * STG);
        #pragma unroll
        for (int i = 0; i < 4; i++) {
            int idx = tid + i * 256;
            int r = idx >> 3, c = (idx & 7) * 4;
            cp_async16(base + (unsigned)(r * AP + c) * 4,
                       A + (size_t)(m0 + r) * lda + k0 + c, (k0 + c < K));
        }
        #pragma unroll
        for (int i = 0; i < 4; i++) {
            int idx = tid + i * 256;
            int r = idx >> 3, c = (idx & 7) * 4;
            bool v = (n0 + r < N) && (k0 + c < K);
            cp_async16(base + (unsigned)(ASZ + r * AP + c) * 4,
                       B + (size_t)(n0 + r) * ldb + k0 + c, v);
        }
        asm volatile("cp.async.commit_group;");
    };

    load_stage(0, 0);
    if (nk > 1) load_stage(1, BK);

    for (int kt = 0; kt < nk; kt++) {
        int s = kt % 3;
        if (kt + 1 < nk) asm volatile("cp.async.wait_group 1;");
        else             asm volatile("cp.async.wait_group 0;");
        __syncthreads();

        if (kt + 2 < nk) load_stage((kt + 2) % 3, (kt + 2) * BK);

        if (SMODE) {
            // exp-transform this stage's A tile in smem (overlaps cp.async)
            float* As = sm + s * STG;
            #pragma unroll
            for (int i = 0; i < 4; i++) {
                int idx = tid + i * 256;
                int r = idx >> 3, c = (idx & 7) * 4;
                float4* p = reinterpret_cast<float4*>(As + r * AP + c);
                float4 v = *p;
                v.x = __expf(v.x - rowm[i]);
                v.y = __expf(v.y - rowm[i]);
                v.z = __expf(v.z - rowm[i]);
                v.w = __expf(v.w - rowm[i]);
                *p = v;
            }
            __syncthreads();
        }

        unsigned aBase = smem_u32(sm + s * STG)
                       + (unsigned)((wm + lrow) * AP + lcol) * 4;
        unsigned bBase = smem_u32(sm + s * STG + ASZ)
                       + (unsigned)((wn + lrow) * AP + lcol) * 4;

        #pragma unroll
        for (int kk = 0; kk < BK; kk += 8) {
            uint32_t ar[4][4];
            #pragma unroll
            for (int mt = 0; mt < 4; mt++)
                ldsm_x4(ar[mt], aBase + (unsigned)(mt * 16 * AP + kk) * 4);
            uint32_t brq[2][4];
            #pragma unroll
            for (int nh = 0; nh < 2; nh++)
                ldsm_x4(brq[nh], bBase + (unsigned)(nh * 16 * AP + kk) * 4);

            #pragma unroll
            for (int mt = 0; mt < 4; mt++) {
                #pragma unroll
                for (int nt = 0; nt < 4; nt++) {
                    uint32_t bb[2] = { brq[nt >> 1][nt & 1], brq[nt >> 1][(nt & 1) + 2] };
                    mma8(acc[mt][nt], ar[mt], bb);
                }
            }
        }
    }

    #pragma unroll
    for (int mt = 0; mt < 4; mt++) {
        #pragma unroll
        for (int nt = 0; nt < 4; nt++) {
            int row0 = m0 + wm + mt * 16 + g;
            int col  = n0 + wn + nt * 8 + 2 * tg;
            float s0 = alpha, s1 = alpha;
            if (SMODE) {
                s0 = st[row0].y;
                s1 = st[row0 + 8].y;
            }
            if (col + 1 < N) {
                float b0 = bias ? bias[col]     : 0.f;
                float b1 = bias ? bias[col + 1] : 0.f;
                float2 v0 = make_float2(s0 * acc[mt][nt][0] + b0,
                                        s0 * acc[mt][nt][1] + b1);
                float2 v1 = make_float2(s1 * acc[mt][nt][2] + b0,
                                        s1 * acc[mt][nt][3] + b1);
                *reinterpret_cast<float2*>(C + (size_t)row0 * ldc + col) = v0;
                *reinterpret_cast<float2*>(C + (size_t)(row0 + 8) * ldc + col) = v1;
            } else if (col < N) {
                float b0 = bias ? bias[col] : 0.f;
                C[(size_t)row0 * ldc + col]       = s0 * acc[mt][nt][0] + b0;
                C[(size_t)(row0 + 8) * ldc + col] = s1 * acc[mt][nt][2] + b0;
            }
        }
    }
}

// ---------------------------------------------------------------------------
__device__ __forceinline__ float warp_max(float v) {
    #pragma unroll
    for (int o = 16; o > 0; o >>= 1) v = fmaxf(v, __shfl_xor_sync(0xffffffffu, v, o));
    return v;
}
__device__ __forceinline__ float warp_sum(float v) {
    #pragma unroll
    for (int o = 16; o > 0; o >>= 1) v += __shfl_xor_sync(0xffffffffu, v, o);
    return v;
}

// ---------------------------------------------------------------------------
// Row stats: per score-row (max, 1/sum_exp). Read-only pass over scores.
// grid (SEQ, 2), 256 threads.
// ---------------------------------------------------------------------------
__global__ __launch_bounds__(256) void row_stats_kernel(
    const float* __restrict__ Sm, float2* __restrict__ stats)
{
    size_t off = ((size_t)blockIdx.y * SEQ + blockIdx.x) * SEQ;
    const float4* row4 = reinterpret_cast<const float4*>(Sm + off);
    const int t = threadIdx.x;
    const int lane = t & 31, wid = t >> 5;

    float4 v[4];
    #pragma unroll
    for (int i = 0; i < 4; i++) v[i] = row4[t + 256 * i];

    float m = -3.4e38f;
    #pragma unroll
    for (int i = 0; i < 4; i++)
        m = fmaxf(m, fmaxf(fmaxf(v[i].x, v[i].y), fmaxf(v[i].z, v[i].w)));

    __shared__ float red[8];
    m = warp_max(m);
    if (lane == 0) red[wid] = m;
    __syncthreads();
    float bm = red[0];
    #pragma unroll
    for (int k = 1; k < 8; k++) bm = fmaxf(bm, red[k]);

    float s = 0.f;
    #pragma unroll
    for (int i = 0; i < 4; i++) {
        s += __expf(v[i].x - bm) + __expf(v[i].y - bm)
           + __expf(v[i].z - bm) + __expf(v[i].w - bm);
    }
    s = warp_sum(s);
    __syncthreads();
    if (lane == 0) red[wid] = s;
    __syncthreads();
    float bs = 0.f;
    #pragma unroll
    for (int k = 0; k < 8; k++) bs += red[k];

    if (t == 0)
        stats[blockIdx.y * SEQ + blockIdx.x] = make_float2(bm, 1.f / bs);
}

// ---------------------------------------------------------------------------
__global__ __launch_bounds__(128) void ln_add_kernel(
    const float* __restrict__ s1, const float* __restrict__ s2,
    const float* __restrict__ g, const float* __restrict__ b,
    float* __restrict__ dst)
{
    const int wid = threadIdx.x >> 5, lane = threadIdx.x & 31;
    const int row = blockIdx.x * 4 + wid;
    const size_t base = ((size_t)blockIdx.y * SEQ + row) * VECT;

    float v[10];
    float s = 0.f;
    #pragma unroll
    for (int i = 0; i < 10; i++) {
        int j = lane + 32 * i;
        float x = 0.f;
        if (j < VECT) x = s1[base + j] + s2[base + j];
        v[i] = x; s += x;
    }
    s = warp_sum(s);
    float mean = s * (1.f / VECT);

    float var = 0.f;
    #pragma unroll
    for (int i = 0; i < 10; i++) {
        int j = lane + 32 * i;
        if (j < VECT) { float d = v[i] - mean; var += d * d; }
    }
    var = warp_sum(var) * (1.f / VECT);
    float inv = rsqrtf(var + 1e-5f);

    #pragma unroll
    for (int i = 0; i < 10; i++) {
        int j = lane + 32 * i;
        if (j < VECT) dst[base + j] = g[j] * (v[i] - mean) * inv + b[j];
    }
}

// ---------------------------------------------------------------------------
// GRU recurrence. 2 blocks, 384 threads (round-9 proven layout) + 2-step
// gx register lookahead (covers DRAM latency; +2 regs, no spill risk).
// Gate-parallel: thread t owns w_hh row t (gate = t>>7). r/z threads compute
// their sigmoid pre-barrier; n-threads own h in registers.
// ---------------------------------------------------------------------------
__global__ __launch_bounds__(384, 1) void gru_kernel(
    const float* __restrict__ whh1, const float* __restrict__ bhh1,
    const float* __restrict__ whh2, const float* __restrict__ bhh2)
{
    const int b = blockIdx.x;
    const float* whh = b ? whh2 : whh1;
    const float* bhh = b ? bhh2 : bhh1;
    const float* gx  = g_gx + (size_t)b * SEQ * G3;
    const int t = threadIdx.x;
    const int gate = t >> 7;         // 0=r, 1=z, 2=n
    const int hid  = t & 127;

    ull wp[64];
    const ull* w2 = reinterpret_cast<const ull*>(whh + t * HID);
    #pragma unroll
    for (int j = 0; j < 64; j++) wp[j] = w2[j];
    const float bh = bhh[t];

    __shared__ __align__(16) float hsh[HID];
    __shared__ float rsh[HID];
    __shared__ float zsh[HID];

    float hcur = 0.f;                 // live only in n-threads
    if (t < HID) hsh[t] = 0.f;
    __syncthreads();

    const float* gxp = gx + t;

    // 2-step lookahead input pipeline
    float xv0 = __ldg(gxp);                       // step 0
    float xv1 = __ldg(gxp + G3);                  // step 1

    #pragma unroll 1
    for (int step = 0; step < SEQ; step++) {
        float xv = xv0;
        xv0 = xv1;
        xv1 = (step + 2 < SEQ) ? __ldg(gxp + (size_t)(step + 2) * G3) : 0.f;

        // gh_t = dot(whh_t, h) + bhh_t  (4 independent FFMA2 chains)
        ull a0 = 0ull, a1 = 0ull, a2 = 0ull, a3 = 0ull;
        const ulonglong2* h2 = reinterpret_cast<const ulonglong2*>(hsh);
        #pragma unroll
        for (int j = 0; j < 16; j++) {
            ulonglong2 hva = h2[2 * j];
            ulonglong2 hvb = h2[2 * j + 1];
            asm("fma.rn.f32x2 %0, %1, %2, %0;" : "+l"(a0) : "l"(wp[4 * j]),     "l"(hva.x));
            asm("fma.rn.f32x2 %0, %1, %2, %0;" : "+l"(a1) : "l"(wp[4 * j + 1]), "l"(hva.y));
            asm("fma.rn.f32x2 %0, %1, %2, %0;" : "+l"(a2) : "l"(wp[4 * j + 2]), "l"(hvb.x));
            asm("fma.rn.f32x2 %0, %1, %2, %0;" : "+l"(a3) : "l"(wp[4 * j + 3]), "l"(hvb.y));
        }
        float l0, h0, l1, h1, l2, h2f, l3, h3;
        asm("mov.b64 {%0,%1}, %2;" : "=f"(l0), "=f"(h0) : "l"(a0));
        asm("mov.b64 {%0,%1}, %2;" : "=f"(l1), "=f"(h1) : "l"(a1));
        asm("mov.b64 {%0,%1}, %2;" : "=f"(l2), "=f"(h2f) : "l"(a2));
        asm("mov.b64 {%0,%1}, %2;" : "=f"(l3), "=f"(h3) : "l"(a3));
        float ghv = ((l0 + h0) + (l1 + h1)) + ((l2 + h2f) + (l3 + h3)) + bh;

        // r/z: finish gate pre-barrier (overlaps other warps' FMA issue)
        if (gate == 0) {
            rsh[hid] = __fdividef(1.f, 1.f + __expf(-(xv + ghv)));
        } else if (gate == 1) {
            zsh[hid] = __fdividef(1.f, 1.f + __expf(-(xv + ghv)));
        }
        __syncthreads();

        // n-threads: tanh + state update (h lives in their registers)
        if (gate == 2) {
            float r = rsh[hid], z = zsh[hid];
            float narg = xv + r * ghv;
            float e2 = __expf(2.f * narg);
            float n = 1.f - __fdividef(2.f, e2 + 1.f);
            hcur = n + z * (hcur - n);
            hsh[hid] = hcur;
        }
        __syncthreads();
    }
    if (gate == 2) g_hcat[b * HID + hid] = hcur;
}

// ---------------------------------------------------------------------------
__global__ __launch_bounds__(256) void head_kernel(
    const float* __restrict__ fc1_w, const float* __restrict__ fc1_b,
    const float* __restrict__ fc2_w, const float* __restrict__ fc2_b,
    float* __restrict__ out)
{
    __shared__ float hs[256], ys[256], ls[3];
    const int t = threadIdx.x;
    hs[t] = g_hcat[t];
    __syncthreads();

    float acc = fc1_b[t];
    #pragma unroll 8
    for (int j = 0; j < 256; j++) acc += fc1_w[t * 256 + j] * hs[j];
    ys[t] = fmaxf(acc, 0.f);
    __syncthreads();

    if (t < 3) {
        float a = fc2_b[t];
        for (int j = 0; j < 256; j++) a += fc2_w[t * 256 + j] * ys[j];
        ls[t] = a;
    }
    __syncthreads();

    if (t == 0) {
        float m = fmaxf(ls[0], fmaxf(ls[1], ls[2]));
        float s = expf(ls[0] - m) + expf(ls[1] - m) + expf(ls[2] - m);
        float lse = m + logf(s);
        out[0] = ls[0] - lse; out[1] = ls[1] - lse; out[2] = ls[2] - lse;
    }
}

// ---------------------------------------------------------------------------
extern "C" void kernel_launch(void* const* d_in, const int* in_sizes, int n_in,
                              void* d_out, int out_size)
{
    (void)in_sizes; (void)n_in; (void)out_size;

    const float* x1     = (const float*)d_in[0];
    const float* x2     = (const float*)d_in[1];
    const float* q_w    = (const float*)d_in[2];
    const float* q_b    = (const float*)d_in[3];
    const float* k_w    = (const float*)d_in[4];
    const float* k_b    = (const float*)d_in[5];
    const float* v_w    = (const float*)d_in[6];
    const float* v_b    = (const float*)d_in[7];
    const float* aln_g  = (const float*)d_in[8];
    const float* aln_b  = (const float*)d_in[9];
    const float* w_w    = (const float*)d_in[10];
    const float* w_b    = (const float*)d_in[11];
    const float* mln_g  = (const float*)d_in[12];
    const float* mln_b  = (const float*)d_in[13];
    const float* g1_wih = (const float*)d_in[14];
    const float* g1_whh = (const float*)d_in[15];
    const float* g1_bih = (const float*)d_in[16];
    const float* g1_bhh = (const float*)d_in[17];
    const float* g2_wih = (const float*)d_in[18];
    const float* g2_whh = (const float*)d_in[19];
    const float* g2_bih = (const float*)d_in[20];
    const float* g2_bhh = (const float*)d_in[21];
    const float* fc1_w  = (const float*)d_in[22];
    const float* fc1_b  = (const float*)d_in[23];
    const float* fc2_w  = (const float*)d_in[24];
    const float* fc2_b  = (const float*)d_in[25];
    float* out = (float*)d_out;

    void *pv;
    cudaGetSymbolAddress(&pv, g_x);      float* p_x      = (float*)pv;
    cudaGetSymbolAddress(&pv, g_cur);    float* p_cur    = (float*)pv;
    cudaGetSymbolAddress(&pv, g_qkv);    float* p_qkv    = (float*)pv;
    cudaGetSymbolAddress(&pv, g_vt);     float* p_vt     = (float*)pv;
    cudaGetSymbolAddress(&pv, g_attn);   float* p_attn   = (float*)pv;
    cudaGetSymbolAddress(&pv, g_h);      float* p_h      = (float*)pv;
    cudaGetSymbolAddress(&pv, g_tmp);    float* p_tmp    = (float*)pv;
    cudaGetSymbolAddress(&pv, g_scores); float* p_scores = (float*)pv;
    cudaGetSymbolAddress(&pv, g_stats);  float2* p_stats = (float2*)pv;
    cudaGetSymbolAddress(&pv, g_gx);     float* p_gx     = (float*)pv;
    cudaGetSymbolAddress(&pv, g_wqkv);   float* p_wqkv   = (float*)pv;
    cudaGetSymbolAddress(&pv, g_bqkv);   float* p_bqkv   = (float*)pv;
    cudaGetSymbolAddress(&pv, g_wih);    float* p_wih    = (float*)pv;
    cudaGetSymbolAddress(&pv, g_bih);    float* p_bih    = (float*)pv;

    const ll SV = (ll)SEQ * VECT;
    const ll S9 = (ll)SEQ * 3 * VECT;
    const ll SS = (ll)SEQ * SEQ;
    const int N9 = 3 * VECT;
    const float inv_scale = 0.05773502691896258f;   // 1/sqrt(300)

    const int SMEM_MMA = 3 * (2 * 128 * 36) * 4;    // 110592 B
    cudaFuncSetAttribute(mma_bt<false>, cudaFuncAttributeMaxDynamicSharedMemorySize, SMEM_MMA);
    cudaFuncSetAttribute(mma_bt<true>,  cudaFuncAttributeMaxDynamicSharedMemorySize, SMEM_MMA);

    init_kernel<<<(2 * SEQ * VECT + 255) / 256, 256>>>(x1, x2);
    {
        int tot = 3 * VECT * VECT + 3 * VECT + 2 * G3 * VECT + 2 * G3;
        pack_kernel<<<(tot + 255) / 256, 256>>>(q_w, q_b, k_w, k_b, v_w, v_b,
                                                g1_wih, g1_bih, g2_wih, g2_bih);
    }

    dim3 gqkv(8, 32, 2);    // QKV proj: N=900 -> 8 tiles of 128
    dim3 gqk (32, 32, 2);   // QK^T: 4096x4096
    dim3 gav (3, 32, 2);    // A·V: N=300
    dim3 gw  (3, 32, 2);    // W proj
    dim3 gtr (10, 128, 2);  // V transpose

    for (int s = 0; s < NSTACK; s++) {
        mma_bt<false><<<gqkv, 256, SMEM_MMA>>>(p_cur, p_wqkv, p_qkv, SEQ, N9, VECT,
                                               VECT, VECT, N9, SV, 0, S9,
                                               p_bqkv, 0, 1.f, nullptr);
        mma_bt<false><<<gqk, 256, SMEM_MMA>>>(p_qkv, p_qkv + VECT, p_scores, SEQ, SEQ, VECT,
                                              N9, N9, SEQ, S9, S9, SS,
                                              nullptr, 0, inv_scale, nullptr);
        row_stats_kernel<<<dim3(SEQ, 2), 256>>>(p_scores, p_stats);

        transpose_kernel<<<gtr, 256>>>(p_qkv + 2 * VECT, p_vt, N9, S9, SV);
        // fused softmax + A·V: exp in smem, 1/sum in epilogue
        mma_bt<true><<<gav, 256, SMEM_MMA>>>(p_scores, p_vt, p_attn, SEQ, VECT, SEQ,
                                             SEQ, SEQ, VECT, SS, SV, SV,
                                             nullptr, 0, 1.f, p_stats);

        ln_add_kernel<<<dim3(SEQ / 4, 2), 128>>>(p_attn, p_cur, aln_g, aln_b, p_h);
        mma_bt<false><<<gw, 256, SMEM_MMA>>>(p_h, w_w, p_tmp, SEQ, VECT, VECT,
                                             VECT, VECT, VECT, SV, 0, SV,
                                             w_b, 0, 1.f, nullptr);
        ln_add_kernel<<<dim3(SEQ / 4, 2), 128>>>(p_tmp, p_x, mln_g, mln_b, p_cur);
    }

    dim3 gg(3, 32, 2);
    mma_bt<false><<<gg, 256, SMEM_MMA>>>(p_cur, p_wih, p_gx, SEQ, G3, VECT,
                                         VECT, VECT, G3, SV, (ll)G3 * VECT, (ll)SEQ * G3,
                                         p_bih, G3, 1.f, nullptr);
    gru_kernel<<<2, 384>>>(g1_whh, g1_bhh, g2_whh, g2_bhh);
    head_kernel<<<1, 256>>>(fc1_w, fc1_b, fc2_w, fc2_b, out);
}

// round 14
// speedup vs baseline: 2.5990x; 1.0134x over previous
#include <cuda_runtime.h>
#include <cstdint>

#define SEQ   4096
#define VECT  300
#define HID   128
#define G3    384
#define NSTACK 3

typedef unsigned long long ull;
typedef long long ll;

// ---------------------------------------------------------------------------
// Scratch (static device globals — allocation-free)
// ---------------------------------------------------------------------------
__device__ float g_x    [2 * SEQ * VECT];
__device__ float g_cur  [2 * SEQ * VECT];
__device__ float g_qkv  [2ll * SEQ * 3 * VECT];   // packed [seq][row][900]: Q|K|V
__device__ float g_vt   [2 * SEQ * VECT];         // V^T per seq: [VECT][SEQ]
__device__ float g_attn [2 * SEQ * VECT];
__device__ float g_h    [2 * SEQ * VECT];
__device__ float g_tmp  [2 * SEQ * VECT];
__device__ float g_scores[2ll * SEQ * SEQ];
__device__ float g_gx   [2 * SEQ * G3];
__device__ float g_hcat [2 * HID];
// packed weights
__device__ float g_wqkv [3 * VECT * VECT];
__device__ float g_bqkv [3 * VECT];
__device__ float g_wih  [2 * G3 * VECT];
__device__ float g_bih  [2 * G3];

// ---------------------------------------------------------------------------
__global__ void init_kernel(const float* __restrict__ x1, const float* __restrict__ x2)
{
    int i = blockIdx.x * blockDim.x + threadIdx.x;
    const int n = SEQ * VECT;
    if (i < n) {
        float v = x1[i];
        g_x[i] = v; g_cur[i] = v;
    } else if (i < 2 * n) {
        float v = x2[i - n];
        g_x[i] = v; g_cur[i] = v;
    }
}

// ---------------------------------------------------------------------------
__global__ void pack_kernel(
    const float* __restrict__ qw, const float* __restrict__ qb,
    const float* __restrict__ kw, const float* __restrict__ kb,
    const float* __restrict__ vw, const float* __restrict__ vb,
    const float* __restrict__ w1, const float* __restrict__ b1,
    const float* __restrict__ w2, const float* __restrict__ b2)
{
    const int N1 = 3 * VECT * VECT;
    const int N2 = 3 * VECT;
    const int N3 = 2 * G3 * VECT;
    const int N4 = 2 * G3;
    int i = blockIdx.x * blockDim.x + threadIdx.x;
    if (i < N1) {
        int row = i / VECT, col = i % VECT;
        float v;
        if (row < VECT)            v = qw[row * VECT + col];
        else if (row < 2 * VECT)   v = kw[(row - VECT) * VECT + col];
        else                       v = vw[(row - 2 * VECT) * VECT + col];
        g_wqkv[i] = v;
    } else if (i < N1 + N2) {
        int r = i - N1;
        g_bqkv[r] = (r < VECT) ? qb[r] : (r < 2 * VECT) ? kb[r - VECT] : vb[r - 2 * VECT];
    } else if (i < N1 + N2 + N3) {
        int j = i - N1 - N2;
        g_wih[j] = (j < G3 * VECT) ? w1[j] : w2[j - G3 * VECT];
    } else if (i < N1 + N2 + N3 + N4) {
        int j = i - N1 - N2 - N3;
        g_bih[j] = (j < G3) ? b1[j] : b2[j - G3];
    }
}

// ---------------------------------------------------------------------------
// Transpose: dst[c][r] = src[r][c]. src [SEQ, VECT] (ld=lds), dst [VECT][SEQ].
// ---------------------------------------------------------------------------
__global__ __launch_bounds__(256) void transpose_kernel(
    const float* __restrict__ src, float* __restrict__ dst,
    int lds, ll sSrc, ll sDst)
{
    __shared__ float t[32][33];
    src += (ll)blockIdx.z * sSrc;
    dst += (ll)blockIdx.z * sDst;
    const int r0 = blockIdx.y * 32, c0 = blockIdx.x * 32;
    const int x = threadIdx.x & 31, y = threadIdx.x >> 5;

    #pragma unroll
    for (int i = 0; i < 4; i++) {
        int col = c0 + x;
        if (col < VECT) t[y + 8 * i][x] = src[(size_t)(r0 + y + 8 * i) * lds + col];
    }
    __syncthreads();
    #pragma unroll
    for (int i = 0; i < 4; i++) {
        int c = c0 + y + 8 * i;
        if (c < VECT) dst[(size_t)c * SEQ + r0 + x] = t[x][y + 8 * i];
    }
}

// ---------------------------------------------------------------------------
// MMA helpers
// ---------------------------------------------------------------------------
__device__ __forceinline__ unsigned smem_u32(const void* p)
{
    return (unsigned)__cvta_generic_to_shared(p);
}
__device__ __forceinline__ void cp_async16(unsigned dst, const float* src, bool valid)
{
    int sz = valid ? 16 : 0;   // src-size 0 -> zero-fill 16B
    asm volatile("cp.async.cg.shared.global [%0], [%1], 16, %2;\n"
                 :: "r"(dst), "l"(src), "r"(sz));
}
__device__ __forceinline__ void ldsm_x4(uint32_t* r, unsigned addr)
{
    asm volatile("ldmatrix.sync.aligned.m8n8.x4.shared.b16 {%0,%1,%2,%3}, [%4];"
                 : "=r"(r[0]), "=r"(r[1]), "=r"(r[2]), "=r"(r[3]) : "r"(addr));
}
__device__ __forceinline__ void mma8(float* c, const uint32_t* a, const uint32_t* b)
{
    asm volatile(
        "mma.sync.aligned.m16n8k8.row.col.f32.tf32.tf32.f32 "
        "{%0,%1,%2,%3}, {%4,%5,%6,%7}, {%8,%9}, {%0,%1,%2,%3};"
        : "+f"(c[0]), "+f"(c[1]), "+f"(c[2]), "+f"(c[3])
        : "r"(a[0]), "r"(a[1]), "r"(a[2]), "r"(a[3]), "r"(b[0]), "r"(b[1]));
}

// ---------------------------------------------------------------------------
// TF32 GEMM: C[M,N] = alpha*A[M,K]*B[N,K]^T (+bias), 128x128x32, 3-stage.
// M % 128 == 0 assumed.
// ---------------------------------------------------------------------------
__global__ __launch_bounds__(256, 2) void mma_bt(
    const float* __restrict__ A, const float* __restrict__ B, float* __restrict__ C,
    int M, int N, int K, int lda, int ldb, int ldc,
    ll sAb, ll sBb, ll sCb,
    const float* __restrict__ bias, ll sBiasb, float alpha)
{
    constexpr int BM = 128, BN = 128, BK = 32, AP = 36;
    constexpr int ASZ = BM * AP;
    constexpr int STG = 2 * ASZ;

    extern __shared__ float sm[];

    A += (ll)blockIdx.z * sAb;
    B += (ll)blockIdx.z * sBb;
    C += (ll)blockIdx.z * sCb;
    if (bias) bias += (ll)blockIdx.z * sBiasb;

    const int m0 = blockIdx.y * BM, n0 = blockIdx.x * BN;
    const int tid = threadIdx.x, lane = tid & 31, warp = tid >> 5;
    const int g = lane >> 2, tg = lane & 3;
    const int wm = (warp & 1) * 64, wn = (warp >> 1) * 32;

    const int lm   = lane >> 3;
    const int lrow = (lm & 1) * 8 + (lane & 7);
    const int lcol = (lm >> 1) * 4;

    float acc[4][4][4] = {};
    const int nk = (K + BK - 1) / BK;

    auto load_stage = [&](int s, int k0) {
        unsigned base = smem_u32(sm + s * STG);
        #pragma unroll
        for (int i = 0; i < 4; i++) {
            int idx = tid + i * 256;
            int r = idx >> 3, c = (idx & 7) * 4;
            cp_async16(base + (unsigned)(r * AP + c) * 4,
                       A + (size_t)(m0 + r) * lda + k0 + c, (k0 + c < K));
        }
        #pragma unroll
        for (int i = 0; i < 4; i++) {
            int idx = tid + i * 256;
            int r = idx >> 3, c = (idx & 7) * 4;
            bool v = (n0 + r < N) && (k0 + c < K);
            cp_async16(base + (unsigned)(ASZ + r * AP + c) * 4,
                       B + (size_t)(n0 + r) * ldb + k0 + c, v);
        }
        asm volatile("cp.async.commit_group;");
    };

    load_stage(0, 0);
    if (nk > 1) load_stage(1, BK);

    for (int kt = 0; kt < nk; kt++) {
        int s = kt % 3;
        if (kt + 1 < nk) asm volatile("cp.async.wait_group 1;");
        else             asm volatile("cp.async.wait_group 0;");
        __syncthreads();

        if (kt + 2 < nk) load_stage((kt + 2) % 3, (kt + 2) * BK);

        unsigned aBase = smem_u32(sm + s * STG)
                       + (unsigned)((wm + lrow) * AP + lcol) * 4;
        unsigned bBase = smem_u32(sm + s * STG + ASZ)
                       + (unsigned)((wn + lrow) * AP + lcol) * 4;

        #pragma unroll
        for (int kk = 0; kk < BK; kk += 8) {
            uint32_t ar[4][4];
            #pragma unroll
            for (int mt = 0; mt < 4; mt++)
                ldsm_x4(ar[mt], aBase + (unsigned)(mt * 16 * AP + kk) * 4);
            uint32_t brq[2][4];
            #pragma unroll
            for (int nh = 0; nh < 2; nh++)
                ldsm_x4(brq[nh], bBase + (unsigned)(nh * 16 * AP + kk) * 4);

            #pragma unroll
            for (int mt = 0; mt < 4; mt++) {
                #pragma unroll
                for (int nt = 0; nt < 4; nt++) {
                    uint32_t bb[2] = { brq[nt >> 1][nt & 1], brq[nt >> 1][(nt & 1) + 2] };
                    mma8(acc[mt][nt], ar[mt], bb);
                }
            }
        }
    }

    #pragma unroll
    for (int mt = 0; mt < 4; mt++) {
        #pragma unroll
        for (int nt = 0; nt < 4; nt++) {
            int row0 = m0 + wm + mt * 16 + g;
            int col  = n0 + wn + nt * 8 + 2 * tg;
            if (col + 1 < N) {
                float b0 = bias ? bias[col]     : 0.f;
                float b1 = bias ? bias[col + 1] : 0.f;
                float2 v0 = make_float2(alpha * acc[mt][nt][0] + b0,
                                        alpha * acc[mt][nt][1] + b1);
                float2 v1 = make_float2(alpha * acc[mt][nt][2] + b0,
                                        alpha * acc[mt][nt][3] + b1);
                *reinterpret_cast<float2*>(C + (size_t)row0 * ldc + col) = v0;
                *reinterpret_cast<float2*>(C + (size_t)(row0 + 8) * ldc + col) = v1;
            } else if (col < N) {
                float b0 = bias ? bias[col] : 0.f;
                C[(size_t)row0 * ldc + col]       = alpha * acc[mt][nt][0] + b0;
                C[(size_t)(row0 + 8) * ldc + col] = alpha * acc[mt][nt][2] + b0;
            }
        }
    }
}

// ---------------------------------------------------------------------------
__device__ __forceinline__ float warp_max(float v) {
    #pragma unroll
    for (int o = 16; o > 0; o >>= 1) v = fmaxf(v, __shfl_xor_sync(0xffffffffu, v, o));
    return v;
}
__device__ __forceinline__ float warp_sum(float v) {
    #pragma unroll
    for (int o = 16; o > 0; o >>= 1) v += __shfl_xor_sync(0xffffffffu, v, o);
    return v;
}

__global__ __launch_bounds__(256) void softmax_kernel(float* __restrict__ Sm)
{
    size_t off = ((size_t)blockIdx.y * SEQ + blockIdx.x) * SEQ;
    float4* row4 = reinterpret_cast<float4*>(Sm + off);
    const int t = threadIdx.x;
    const int lane = t & 31, wid = t >> 5;

    float4 v[4];
    #pragma unroll
    for (int i = 0; i < 4; i++) v[i] = row4[t + 256 * i];

    float m = -3.4e38f;
    #pragma unroll
    for (int i = 0; i < 4; i++)
        m = fmaxf(m, fmaxf(fmaxf(v[i].x, v[i].y), fmaxf(v[i].z, v[i].w)));

    __shared__ float red[8];
    m = warp_max(m);
    if (lane == 0) red[wid] = m;
    __syncthreads();
    float bm = red[0];
    #pragma unroll
    for (int k = 1; k < 8; k++) bm = fmaxf(bm, red[k]);

    float s = 0.f;
    #pragma unroll
    for (int i = 0; i < 4; i++) {
        v[i].x = __expf(v[i].x - bm); v[i].y = __expf(v[i].y - bm);
        v[i].z = __expf(v[i].z - bm); v[i].w = __expf(v[i].w - bm);
        s += v[i].x + v[i].y + v[i].z + v[i].w;
    }
    s = warp_sum(s);
    __syncthreads();
    if (lane == 0) red[wid] = s;
    __syncthreads();
    float bs = 0.f;
    #pragma unroll
    for (int k = 0; k < 8; k++) bs += red[k];
    float inv = 1.f / bs;

    #pragma unroll
    for (int i = 0; i < 4; i++) {
        v[i].x *= inv; v[i].y *= inv; v[i].z *= inv; v[i].w *= inv;
        row4[t + 256 * i] = v[i];
    }
}

// ---------------------------------------------------------------------------
__global__ __launch_bounds__(128) void ln_add_kernel(
    const float* __restrict__ s1, const float* __restrict__ s2,
    const float* __restrict__ g, const float* __restrict__ b,
    float* __restrict__ dst)
{
    const int wid = threadIdx.x >> 5, lane = threadIdx.x & 31;
    const int row = blockIdx.x * 4 + wid;
    const size_t base = ((size_t)blockIdx.y * SEQ + row) * VECT;

    float v[10];
    float s = 0.f;
    #pragma unroll
    for (int i = 0; i < 10; i++) {
        int j = lane + 32 * i;
        float x = 0.f;
        if (j < VECT) x = s1[base + j] + s2[base + j];
        v[i] = x; s += x;
    }
    s = warp_sum(s);
    float mean = s * (1.f / VECT);

    float var = 0.f;
    #pragma unroll
    for (int i = 0; i < 10; i++) {
        int j = lane + 32 * i;
        if (j < VECT) { float d = v[i] - mean; var += d * d; }
    }
    var = warp_sum(var) * (1.f / VECT);
    float inv = rsqrtf(var + 1e-5f);

    #pragma unroll
    for (int i = 0; i < 10; i++) {
        int j = lane + 32 * i;
        if (j < VECT) dst[base + j] = g[j] * (v[i] - mean) * inv + b[j];
    }
}

// ---------------------------------------------------------------------------
// GRU recurrence. 2 blocks, 384 threads (round-9 proven layout) + 2-step
// gx register lookahead (covers DRAM latency; +2 regs, no spill risk).
// Gate-parallel: thread t owns w_hh row t (gate = t>>7). r/z threads compute
// their sigmoid pre-barrier; n-threads own h in registers.
// ---------------------------------------------------------------------------
__global__ __launch_bounds__(384, 1) void gru_kernel(
    const float* __restrict__ whh1, const float* __restrict__ bhh1,
    const float* __restrict__ whh2, const float* __restrict__ bhh2)
{
    const int b = blockIdx.x;
    const float* whh = b ? whh2 : whh1;
    const float* bhh = b ? bhh2 : bhh1;
    const float* gx  = g_gx + (size_t)b * SEQ * G3;
    const int t = threadIdx.x;
    const int gate = t >> 7;         // 0=r, 1=z, 2=n
    const int hid  = t & 127;

    ull wp[64];
    const ull* w2 = reinterpret_cast<const ull*>(whh + t * HID);
    #pragma unroll
    for (int j = 0; j < 64; j++) wp[j] = w2[j];
    const float bh = bhh[t];

    __shared__ __align__(16) float hsh[HID];
    __shared__ float rsh[HID];
    __shared__ float zsh[HID];

    float hcur = 0.f;                 // live only in n-threads
    if (t < HID) hsh[t] = 0.f;
    __syncthreads();

    const float* gxp = gx + t;

    // 2-step lookahead input pipeline
    float xv0 = __ldg(gxp);                       // step 0
    float xv1 = __ldg(gxp + G3);                  // step 1

    #pragma unroll 1
    for (int step = 0; step < SEQ; step++) {
        float xv = xv0;
        xv0 = xv1;
        xv1 = (step + 2 < SEQ) ? __ldg(gxp + (size_t)(step + 2) * G3) : 0.f;

        // gh_t = dot(whh_t, h) + bhh_t  (4 independent FFMA2 chains)
        ull a0 = 0ull, a1 = 0ull, a2 = 0ull, a3 = 0ull;
        const ulonglong2* h2 = reinterpret_cast<const ulonglong2*>(hsh);
        #pragma unroll
        for (int j = 0; j < 16; j++) {
            ulonglong2 hva = h2[2 * j];
            ulonglong2 hvb = h2[2 * j + 1];
            asm("fma.rn.f32x2 %0, %1, %2, %0;" : "+l"(a0) : "l"(wp[4 * j]),     "l"(hva.x));
            asm("fma.rn.f32x2 %0, %1, %2, %0;" : "+l"(a1) : "l"(wp[4 * j + 1]), "l"(hva.y));
            asm("fma.rn.f32x2 %0, %1, %2, %0;" : "+l"(a2) : "l"(wp[4 * j + 2]), "l"(hvb.x));
            asm("fma.rn.f32x2 %0, %1, %2, %0;" : "+l"(a3) : "l"(wp[4 * j + 3]), "l"(hvb.y));
        }
        float l0, h0, l1, h1, l2, h2f, l3, h3;
        asm("mov.b64 {%0,%1}, %2;" : "=f"(l0), "=f"(h0) : "l"(a0));
        asm("mov.b64 {%0,%1}, %2;" : "=f"(l1), "=f"(h1) : "l"(a1));
        asm("mov.b64 {%0,%1}, %2;" : "=f"(l2), "=f"(h2f) : "l"(a2));
        asm("mov.b64 {%0,%1}, %2;" : "=f"(l3), "=f"(h3) : "l"(a3));
        float ghv = ((l0 + h0) + (l1 + h1)) + ((l2 + h2f) + (l3 + h3)) + bh;

        // r/z: finish gate pre-barrier (overlaps other warps' FMA issue)
        if (gate == 0) {
            rsh[hid] = __fdividef(1.f, 1.f + __expf(-(xv + ghv)));
        } else if (gate == 1) {
            zsh[hid] = __fdividef(1.f, 1.f + __expf(-(xv + ghv)));
        }
        __syncthreads();

        // n-threads: tanh + state update (h lives in their registers)
        if (gate == 2) {
            float r = rsh[hid], z = zsh[hid];
            float narg = xv + r * ghv;
            float e2 = __expf(2.f * narg);
            float n = 1.f - __fdividef(2.f, e2 + 1.f);
            hcur = n + z * (hcur - n);
            hsh[hid] = hcur;
        }
        __syncthreads();
    }
    if (gate == 2) g_hcat[b * HID + hid] = hcur;
}

// ---------------------------------------------------------------------------
__global__ __launch_bounds__(256) void head_kernel(
    const float* __restrict__ fc1_w, const float* __restrict__ fc1_b,
    const float* __restrict__ fc2_w, const float* __restrict__ fc2_b,
    float* __restrict__ out)
{
    __shared__ float hs[256], ys[256], ls[3];
    const int t = threadIdx.x;
    hs[t] = g_hcat[t];
    __syncthreads();

    float acc = fc1_b[t];
    #pragma unroll 8
    for (int j = 0; j < 256; j++) acc += fc1_w[t * 256 + j] * hs[j];
    ys[t] = fmaxf(acc, 0.f);
    __syncthreads();

    if (t < 3) {
        float a = fc2_b[t];
        for (int j = 0; j < 256; j++) a += fc2_w[t * 256 + j] * ys[j];
        ls[t] = a;
    }
    __syncthreads();

    if (t == 0) {
        float m = fmaxf(ls[0], fmaxf(ls[1], ls[2]));
        float s = expf(ls[0] - m) + expf(ls[1] - m) + expf(ls[2] - m);
        float lse = m + logf(s);
        out[0] = ls[0] - lse; out[1] = ls[1] - lse; out[2] = ls[2] - lse;
    }
}

// ---------------------------------------------------------------------------
extern "C" void kernel_launch(void* const* d_in, const int* in_sizes, int n_in,
                              void* d_out, int out_size)
{
    (void)in_sizes; (void)n_in; (void)out_size;

    const float* x1     = (const float*)d_in[0];
    const float* x2     = (const float*)d_in[1];
    const float* q_w    = (const float*)d_in[2];
    const float* q_b    = (const float*)d_in[3];
    const float* k_w    = (const float*)d_in[4];
    const float* k_b    = (const float*)d_in[5];
    const float* v_w    = (const float*)d_in[6];
    const float* v_b    = (const float*)d_in[7];
    const float* aln_g  = (const float*)d_in[8];
    const float* aln_b  = (const float*)d_in[9];
    const float* w_w    = (const float*)d_in[10];
    const float* w_b    = (const float*)d_in[11];
    const float* mln_g  = (const float*)d_in[12];
    const float* mln_b  = (const float*)d_in[13];
    const float* g1_wih = (const float*)d_in[14];
    const float* g1_whh = (const float*)d_in[15];
    const float* g1_bih = (const float*)d_in[16];
    const float* g1_bhh = (const float*)d_in[17];
    const float* g2_wih = (const float*)d_in[18];
    const float* g2_whh = (const float*)d_in[19];
    const float* g2_bih = (const float*)d_in[20];
    const float* g2_bhh = (const float*)d_in[21];
    const float* fc1_w  = (const float*)d_in[22];
    const float* fc1_b  = (const float*)d_in[23];
    const float* fc2_w  = (const float*)d_in[24];
    const float* fc2_b  = (const float*)d_in[25];
    float* out = (float*)d_out;

    void *pv;
    cudaGetSymbolAddress(&pv, g_x);      float* p_x      = (float*)pv;
    cudaGetSymbolAddress(&pv, g_cur);    float* p_cur    = (float*)pv;
    cudaGetSymbolAddress(&pv, g_qkv);    float* p_qkv    = (float*)pv;
    cudaGetSymbolAddress(&pv, g_vt);     float* p_vt     = (float*)pv;
    cudaGetSymbolAddress(&pv, g_attn);   float* p_attn   = (float*)pv;
    cudaGetSymbolAddress(&pv, g_h);      float* p_h      = (float*)pv;
    cudaGetSymbolAddress(&pv, g_tmp);    float* p_tmp    = (float*)pv;
    cudaGetSymbolAddress(&pv, g_scores); float* p_scores = (float*)pv;
    cudaGetSymbolAddress(&pv, g_gx);     float* p_gx     = (float*)pv;
    cudaGetSymbolAddress(&pv, g_wqkv);   float* p_wqkv   = (float*)pv;
    cudaGetSymbolAddress(&pv, g_bqkv);   float* p_bqkv   = (float*)pv;
    cudaGetSymbolAddress(&pv, g_wih);    float* p_wih    = (float*)pv;
    cudaGetSymbolAddress(&pv, g_bih);    float* p_bih    = (float*)pv;

    const ll SV = (ll)SEQ * VECT;
    const ll S9 = (ll)SEQ * 3 * VECT;
    const ll SS = (ll)SEQ * SEQ;
    const int N9 = 3 * VECT;
    const float inv_scale = 0.05773502691896258f;   // 1/sqrt(300)

    const int SMEM_MMA = 3 * (2 * 128 * 36) * 4;    // 110592 B
    cudaFuncSetAttribute(mma_bt, cudaFuncAttributeMaxDynamicSharedMemorySize, SMEM_MMA);

    init_kernel<<<(2 * SEQ * VECT + 255) / 256, 256>>>(x1, x2);
    {
        int tot = 3 * VECT * VECT + 3 * VECT + 2 * G3 * VECT + 2 * G3;
        pack_kernel<<<(tot + 255) / 256, 256>>>(q_w, q_b, k_w, k_b, v_w, v_b,
                                                g1_wih, g1_bih, g2_wih, g2_bih);
    }

    dim3 gqkv(8, 32, 2);    // QKV proj: N=900 -> 8 tiles of 128
    dim3 gqk (32, 32, 2);   // QK^T: 4096x4096
    dim3 gav (3, 32, 2);    // A·V: N=300
    dim3 gw  (3, 32, 2);    // W proj
    dim3 gtr (10, 128, 2);  // V transpose

    for (int s = 0; s < NSTACK; s++) {
        mma_bt<<<gqkv, 256, SMEM_MMA>>>(p_cur, p_wqkv, p_qkv, SEQ, N9, VECT,
                                        VECT, VECT, N9, SV, 0, S9,
                                        p_bqkv, 0, 1.f);
        mma_bt<<<gqk, 256, SMEM_MMA>>>(p_qkv, p_qkv + VECT, p_scores, SEQ, SEQ, VECT,
                                       N9, N9, SEQ, S9, S9, SS,
                                       nullptr, 0, inv_scale);
        softmax_kernel<<<dim3(SEQ, 2), 256>>>(p_scores);

        transpose_kernel<<<gtr, 256>>>(p_qkv + 2 * VECT, p_vt, N9, S9, SV);
        mma_bt<<<gav, 256, SMEM_MMA>>>(p_scores, p_vt, p_attn, SEQ, VECT, SEQ,
                                       SEQ, SEQ, VECT, SS, SV, SV,
                                       nullptr, 0, 1.f);

        ln_add_kernel<<<dim3(SEQ / 4, 2), 128>>>(p_attn, p_cur, aln_g, aln_b, p_h);
        mma_bt<<<gw, 256, SMEM_MMA>>>(p_h, w_w, p_tmp, SEQ, VECT, VECT,
                                      VECT, VECT, VECT, SV, 0, SV,
                                      w_b, 0, 1.f);
        ln_add_kernel<<<dim3(SEQ / 4, 2), 128>>>(p_tmp, p_x, mln_g, mln_b, p_cur);
    }

    dim3 gg(3, 32, 2);
    mma_bt<<<gg, 256, SMEM_MMA>>>(p_cur, p_wih, p_gx, SEQ, G3, VECT,
                                  VECT, VECT, G3, SV, (ll)G3 * VECT, (ll)SEQ * G3,
                                  p_bih, G3, 1.f);
    gru_kernel<<<2, 384>>>(g1_whh, g1_bhh, g2_whh, g2_bhh);
    head_kernel<<<1, 256>>>(fc1_w, fc1_b, fc2_w, fc2_b, out);
}

// round 15
// speedup vs baseline: 2.6953x; 1.0371x over previous
#include <cuda_runtime.h>
#include <cstdint>

#define SEQ   4096
#define VECT  300
#define HID   128
#define G3    384
#define NSTACK 3
#define NSPLIT 4
#define KSPLIT (SEQ / NSPLIT)

typedef unsigned long long ull;
typedef long long ll;

// ---------------------------------------------------------------------------
// Scratch (static device globals — allocation-free)
// ---------------------------------------------------------------------------
__device__ float g_x    [2 * SEQ * VECT];
__device__ float g_cur  [2 * SEQ * VECT];
__device__ float g_qkv  [2ll * SEQ * 3 * VECT];   // packed [seq][row][900]: Q|K|V
__device__ float g_vt   [2 * SEQ * VECT];         // V^T per seq: [VECT][SEQ]
__device__ float g_attn [2 * SEQ * VECT];
__device__ float g_h    [2 * SEQ * VECT];
__device__ float g_tmp  [2 * SEQ * VECT];
__device__ float g_scores[2ll * SEQ * SEQ];
__device__ float g_avp  [(ll)2 * NSPLIT * SEQ * VECT];  // split-K partials
__device__ float g_gx   [2 * SEQ * G3];
__device__ float g_hcat [2 * HID];
// packed weights
__device__ float g_wqkv [3 * VECT * VECT];
__device__ float g_bqkv [3 * VECT];
__device__ float g_wih  [2 * G3 * VECT];
__device__ float g_bih  [2 * G3];

// ---------------------------------------------------------------------------
__global__ void init_kernel(const float* __restrict__ x1, const float* __restrict__ x2)
{
    int i = blockIdx.x * blockDim.x + threadIdx.x;
    const int n = SEQ * VECT;
    if (i < n) {
        float v = x1[i];
        g_x[i] = v; g_cur[i] = v;
    } else if (i < 2 * n) {
        float v = x2[i - n];
        g_x[i] = v; g_cur[i] = v;
    }
}

// ---------------------------------------------------------------------------
__global__ void pack_kernel(
    const float* __restrict__ qw, const float* __restrict__ qb,
    const float* __restrict__ kw, const float* __restrict__ kb,
    const float* __restrict__ vw, const float* __restrict__ vb,
    const float* __restrict__ w1, const float* __restrict__ b1,
    const float* __restrict__ w2, const float* __restrict__ b2)
{
    const int N1 = 3 * VECT * VECT;
    const int N2 = 3 * VECT;
    const int N3 = 2 * G3 * VECT;
    const int N4 = 2 * G3;
    int i = blockIdx.x * blockDim.x + threadIdx.x;
    if (i < N1) {
        int row = i / VECT, col = i % VECT;
        float v;
        if (row < VECT)            v = qw[row * VECT + col];
        else if (row < 2 * VECT)   v = kw[(row - VECT) * VECT + col];
        else                       v = vw[(row - 2 * VECT) * VECT + col];
        g_wqkv[i] = v;
    } else if (i < N1 + N2) {
        int r = i - N1;
        g_bqkv[r] = (r < VECT) ? qb[r] : (r < 2 * VECT) ? kb[r - VECT] : vb[r - 2 * VECT];
    } else if (i < N1 + N2 + N3) {
        int j = i - N1 - N2;
        g_wih[j] = (j < G3 * VECT) ? w1[j] : w2[j - G3 * VECT];
    } else if (i < N1 + N2 + N3 + N4) {
        int j = i - N1 - N2 - N3;
        g_bih[j] = (j < G3) ? b1[j] : b2[j - G3];
    }
}

// ---------------------------------------------------------------------------
// Transpose: dst[c][r] = src[r][c]. src [SEQ, VECT] (ld=lds), dst [VECT][SEQ].
// ---------------------------------------------------------------------------
__global__ __launch_bounds__(256) void transpose_kernel(
    const float* __restrict__ src, float* __restrict__ dst,
    int lds, ll sSrc, ll sDst)
{
    __shared__ float t[32][33];
    src += (ll)blockIdx.z * sSrc;
    dst += (ll)blockIdx.z * sDst;
    const int r0 = blockIdx.y * 32, c0 = blockIdx.x * 32;
    const int x = threadIdx.x & 31, y = threadIdx.x >> 5;

    #pragma unroll
    for (int i = 0; i < 4; i++) {
        int col = c0 + x;
        if (col < VECT) t[y + 8 * i][x] = src[(size_t)(r0 + y + 8 * i) * lds + col];
    }
    __syncthreads();
    #pragma unroll
    for (int i = 0; i < 4; i++) {
        int c = c0 + y + 8 * i;
        if (c < VECT) dst[(size_t)c * SEQ + r0 + x] = t[x][y + 8 * i];
    }
}

// ---------------------------------------------------------------------------
// MMA helpers
// ---------------------------------------------------------------------------
__device__ __forceinline__ unsigned smem_u32(const void* p)
{
    return (unsigned)__cvta_generic_to_shared(p);
}
__device__ __forceinline__ void cp_async16(unsigned dst, const float* src, bool valid)
{
    int sz = valid ? 16 : 0;   // src-size 0 -> zero-fill 16B
    asm volatile("cp.async.cg.shared.global [%0], [%1], 16, %2;\n"
                 :: "r"(dst), "l"(src), "r"(sz));
}
__device__ __forceinline__ void ldsm_x4(uint32_t* r, unsigned addr)
{
    asm volatile("ldmatrix.sync.aligned.m8n8.x4.shared.b16 {%0,%1,%2,%3}, [%4];"
                 : "=r"(r[0]), "=r"(r[1]), "=r"(r[2]), "=r"(r[3]) : "r"(addr));
}
__device__ __forceinline__ void mma8(float* c, const uint32_t* a, const uint32_t* b)
{
    asm volatile(
        "mma.sync.aligned.m16n8k8.row.col.f32.tf32.tf32.f32 "
        "{%0,%1,%2,%3}, {%4,%5,%6,%7}, {%8,%9}, {%0,%1,%2,%3};"
        : "+f"(c[0]), "+f"(c[1]), "+f"(c[2]), "+f"(c[3])
        : "r"(a[0]), "r"(a[1]), "r"(a[2]), "r"(a[3]), "r"(b[0]), "r"(b[1]));
}

// ---------------------------------------------------------------------------
// TF32 GEMM: C[M,N] = alpha*A[M,K]*B[N,K]^T (+bias), 128x128x32, 3-stage.
// M % 128 == 0 assumed.
// SPLITZ: blockIdx.z encodes (seq, split): seq = z>>2, split = z&3;
// A/B advance by split*KSPLIT along K, C = base + z*sCb, K = KSPLIT.
// ---------------------------------------------------------------------------
template<bool SPLITZ>
__global__ __launch_bounds__(256, 2) void mma_bt(
    const float* __restrict__ A, const float* __restrict__ B, float* __restrict__ C,
    int M, int N, int K, int lda, int ldb, int ldc,
    ll sAb, ll sBb, ll sCb,
    const float* __restrict__ bias, ll sBiasb, float alpha)
{
    constexpr int BM = 128, BN = 128, BK = 32, AP = 36;
    constexpr int ASZ = BM * AP;
    constexpr int STG = 2 * ASZ;

    extern __shared__ float sm[];

    if (SPLITZ) {
        int seq = blockIdx.z >> 2, sp = blockIdx.z & 3;
        A += (ll)seq * sAb + (ll)sp * KSPLIT;
        B += (ll)seq * sBb + (ll)sp * KSPLIT;
        C += (ll)blockIdx.z * sCb;
    } else {
        A += (ll)blockIdx.z * sAb;
        B += (ll)blockIdx.z * sBb;
        C += (ll)blockIdx.z * sCb;
        if (bias) bias += (ll)blockIdx.z * sBiasb;
    }

    const int m0 = blockIdx.y * BM, n0 = blockIdx.x * BN;
    const int tid = threadIdx.x, lane = tid & 31, warp = tid >> 5;
    const int g = lane >> 2, tg = lane & 3;
    const int wm = (warp & 1) * 64, wn = (warp >> 1) * 32;

    const int lm   = lane >> 3;
    const int lrow = (lm & 1) * 8 + (lane & 7);
    const int lcol = (lm >> 1) * 4;

    float acc[4][4][4] = {};
    const int nk = (K + BK - 1) / BK;

    auto load_stage = [&](int s, int k0) {
        unsigned base = smem_u32(sm + s * STG);
        #pragma unroll
        for (int i = 0; i < 4; i++) {
            int idx = tid + i * 256;
            int r = idx >> 3, c = (idx & 7) * 4;
            cp_async16(base + (unsigned)(r * AP + c) * 4,
                       A + (size_t)(m0 + r) * lda + k0 + c, (k0 + c < K));
        }
        #pragma unroll
        for (int i = 0; i < 4; i++) {
            int idx = tid + i * 256;
            int r = idx >> 3, c = (idx & 7) * 4;
            bool v = (n0 + r < N) && (k0 + c < K);
            cp_async16(base + (unsigned)(ASZ + r * AP + c) * 4,
                       B + (size_t)(n0 + r) * ldb + k0 + c, v);
        }
        asm volatile("cp.async.commit_group;");
    };

    load_stage(0, 0);
    if (nk > 1) load_stage(1, BK);

    for (int kt = 0; kt < nk; kt++) {
        int s = kt % 3;
        if (kt + 1 < nk) asm volatile("cp.async.wait_group 1;");
        else             asm volatile("cp.async.wait_group 0;");
        __syncthreads();

        if (kt + 2 < nk) load_stage((kt + 2) % 3, (kt + 2) * BK);

        unsigned aBase = smem_u32(sm + s * STG)
                       + (unsigned)((wm + lrow) * AP + lcol) * 4;
        unsigned bBase = smem_u32(sm + s * STG + ASZ)
                       + (unsigned)((wn + lrow) * AP + lcol) * 4;

        #pragma unroll
        for (int kk = 0; kk < BK; kk += 8) {
            uint32_t ar[4][4];
            #pragma unroll
            for (int mt = 0; mt < 4; mt++)
                ldsm_x4(ar[mt], aBase + (unsigned)(mt * 16 * AP + kk) * 4);
            uint32_t brq[2][4];
            #pragma unroll
            for (int nh = 0; nh < 2; nh++)
                ldsm_x4(brq[nh], bBase + (unsigned)(nh * 16 * AP + kk) * 4);

            #pragma unroll
            for (int mt = 0; mt < 4; mt++) {
                #pragma unroll
                for (int nt = 0; nt < 4; nt++) {
                    uint32_t bb[2] = { brq[nt >> 1][nt & 1], brq[nt >> 1][(nt & 1) + 2] };
                    mma8(acc[mt][nt], ar[mt], bb);
                }
            }
        }
    }

    #pragma unroll
    for (int mt = 0; mt < 4; mt++) {
        #pragma unroll
        for (int nt = 0; nt < 4; nt++) {
            int row0 = m0 + wm + mt * 16 + g;
            int col  = n0 + wn + nt * 8 + 2 * tg;
            if (col + 1 < N) {
                float b0 = (!SPLITZ && bias) ? bias[col]     : 0.f;
                float b1 = (!SPLITZ && bias) ? bias[col + 1] : 0.f;
                float2 v0 = make_float2(alpha * acc[mt][nt][0] + b0,
                                        alpha * acc[mt][nt][1] + b1);
                float2 v1 = make_float2(alpha * acc[mt][nt][2] + b0,
                                        alpha * acc[mt][nt][3] + b1);
                *reinterpret_cast<float2*>(C + (size_t)row0 * ldc + col) = v0;
                *reinterpret_cast<float2*>(C + (size_t)(row0 + 8) * ldc + col) = v1;
            } else if (col < N) {
                float b0 = (!SPLITZ && bias) ? bias[col] : 0.f;
                C[(size_t)row0 * ldc + col]       = alpha * acc[mt][nt][0] + b0;
                C[(size_t)(row0 + 8) * ldc + col] = alpha * acc[mt][nt][2] + b0;
            }
        }
    }
}

// ---------------------------------------------------------------------------
// Reduce split-K partials: attn[seq][i] = sum_sp avp[(seq*4+sp)][i]
// grid (SEQ*VECT/1024, 2), 256 threads, float4 per thread.
// ---------------------------------------------------------------------------
__global__ __launch_bounds__(256) void av_reduce_kernel(
    const float* __restrict__ part, float* __restrict__ dst)
{
    const ll SV = (ll)SEQ * VECT;
    int i = (blockIdx.x * 256 + threadIdx.x) * 4;
    const float* p = part + (ll)blockIdx.y * NSPLIT * SV + i;
    float4 a = *reinterpret_cast<const float4*>(p);
    float4 b = *reinterpret_cast<const float4*>(p + SV);
    float4 c = *reinterpret_cast<const float4*>(p + 2 * SV);
    float4 d = *reinterpret_cast<const float4*>(p + 3 * SV);
    float4 o;
    o.x = (a.x + b.x) + (c.x + d.x);
    o.y = (a.y + b.y) + (c.y + d.y);
    o.z = (a.z + b.z) + (c.z + d.z);
    o.w = (a.w + b.w) + (c.w + d.w);
    *reinterpret_cast<float4*>(dst + (ll)blockIdx.y * SV + i) = o;
}

// ---------------------------------------------------------------------------
__device__ __forceinline__ float warp_max(float v) {
    #pragma unroll
    for (int o = 16; o > 0; o >>= 1) v = fmaxf(v, __shfl_xor_sync(0xffffffffu, v, o));
    return v;
}
__device__ __forceinline__ float warp_sum(float v) {
    #pragma unroll
    for (int o = 16; o > 0; o >>= 1) v += __shfl_xor_sync(0xffffffffu, v, o);
    return v;
}

__global__ __launch_bounds__(256) void softmax_kernel(float* __restrict__ Sm)
{
    size_t off = ((size_t)blockIdx.y * SEQ + blockIdx.x) * SEQ;
    float4* row4 = reinterpret_cast<float4*>(Sm + off);
    const int t = threadIdx.x;
    const int lane = t & 31, wid = t >> 5;

    float4 v[4];
    #pragma unroll
    for (int i = 0; i < 4; i++) v[i] = row4[t + 256 * i];

    float m = -3.4e38f;
    #pragma unroll
    for (int i = 0; i < 4; i++)
        m = fmaxf(m, fmaxf(fmaxf(v[i].x, v[i].y), fmaxf(v[i].z, v[i].w)));

    __shared__ float red[8];
    m = warp_max(m);
    if (lane == 0) red[wid] = m;
    __syncthreads();
    float bm = red[0];
    #pragma unroll
    for (int k = 1; k < 8; k++) bm = fmaxf(bm, red[k]);

    float s = 0.f;
    #pragma unroll
    for (int i = 0; i < 4; i++) {
        v[i].x = __expf(v[i].x - bm); v[i].y = __expf(v[i].y - bm);
        v[i].z = __expf(v[i].z - bm); v[i].w = __expf(v[i].w - bm);
        s += v[i].x + v[i].y + v[i].z + v[i].w;
    }
    s = warp_sum(s);
    __syncthreads();
    if (lane == 0) red[wid] = s;
    __syncthreads();
    float bs = 0.f;
    #pragma unroll
    for (int k = 0; k < 8; k++) bs += red[k];
    float inv = 1.f / bs;

    #pragma unroll
    for (int i = 0; i < 4; i++) {
        v[i].x *= inv; v[i].y *= inv; v[i].z *= inv; v[i].w *= inv;
        row4[t + 256 * i] = v[i];
    }
}

// ---------------------------------------------------------------------------
__global__ __launch_bounds__(128) void ln_add_kernel(
    const float* __restrict__ s1, const float* __restrict__ s2,
    const float* __restrict__ g, const float* __restrict__ b,
    float* __restrict__ dst)
{
    const int wid = threadIdx.x >> 5, lane = threadIdx.x & 31;
    const int row = blockIdx.x * 4 + wid;
    const size_t base = ((size_t)blockIdx.y * SEQ + row) * VECT;

    float v[10];
    float s = 0.f;
    #pragma unroll
    for (int i = 0; i < 10; i++) {
        int j = lane + 32 * i;
        float x = 0.f;
        if (j < VECT) x = s1[base + j] + s2[base + j];
        v[i] = x; s += x;
    }
    s = warp_sum(s);
    float mean = s * (1.f / VECT);

    float var = 0.f;
    #pragma unroll
    for (int i = 0; i < 10; i++) {
        int j = lane + 32 * i;
        if (j < VECT) { float d = v[i] - mean; var += d * d; }
    }
    var = warp_sum(var) * (1.f / VECT);
    float inv = rsqrtf(var + 1e-5f);

    #pragma unroll
    for (int i = 0; i < 10; i++) {
        int j = lane + 32 * i;
        if (j < VECT) dst[base + j] = g[j] * (v[i] - mean) * inv + b[j];
    }
}

// ---------------------------------------------------------------------------
// GRU recurrence (round-9 proven layout, bias folded into packed acc init,
// f32x2 reduction tree). 2 blocks, 384 threads.
// Gate-parallel: thread t owns w_hh row t (gate = t>>7). r/z threads compute
// their sigmoid pre-barrier; n-threads own h in registers. Early __ldg of gx.
// ---------------------------------------------------------------------------
__global__ __launch_bounds__(384, 1) void gru_kernel(
    const float* __restrict__ whh1, const float* __restrict__ bhh1,
    const float* __restrict__ whh2, const float* __restrict__ bhh2)
{
    const int b = blockIdx.x;
    const float* whh = b ? whh2 : whh1;
    const float* bhh = b ? bhh2 : bhh1;
    const float* gx  = g_gx + (size_t)b * SEQ * G3;
    const int t = threadIdx.x;
    const int gate = t >> 7;         // 0=r, 1=z, 2=n
    const int hid  = t & 127;

    ull wp[64];
    const ull* w2 = reinterpret_cast<const ull*>(whh + t * HID);
    #pragma unroll
    for (int j = 0; j < 64; j++) wp[j] = w2[j];
    const ull bh_pk = (ull)__float_as_uint(bhh[t]);   // bias in low lane of a0

    __shared__ __align__(16) float hsh[HID];
    __shared__ float rsh[HID];
    __shared__ float zsh[HID];

    float hcur = 0.f;                 // live only in n-threads
    if (t < HID) hsh[t] = 0.f;
    __syncthreads();

    const float* gxp = gx + t;

    #pragma unroll 1
    for (int step = 0; step < SEQ; step++) {
        // early input load — consumed ~384 cycles later
        float xv = __ldg(gxp + (size_t)step * G3);

        // gh_t = dot(whh_t, h) + bhh_t  (4 independent FFMA2 chains)
        ull a0 = bh_pk, a1 = 0ull, a2 = 0ull, a3 = 0ull;
        const ulonglong2* h2 = reinterpret_cast<const ulonglong2*>(hsh);
        #pragma unroll
        for (int j = 0; j < 16; j++) {
            ulonglong2 hva = h2[2 * j];
            ulonglong2 hvb = h2[2 * j + 1];
            asm("fma.rn.f32x2 %0, %1, %2, %0;" : "+l"(a0) : "l"(wp[4 * j]),     "l"(hva.x));
            asm("fma.rn.f32x2 %0, %1, %2, %0;" : "+l"(a1) : "l"(wp[4 * j + 1]), "l"(hva.y));
            asm("fma.rn.f32x2 %0, %1, %2, %0;" : "+l"(a2) : "l"(wp[4 * j + 2]), "l"(hvb.x));
            asm("fma.rn.f32x2 %0, %1, %2, %0;" : "+l"(a3) : "l"(wp[4 * j + 3]), "l"(hvb.y));
        }
        ull s01, s23, sA;
        asm("add.rn.f32x2 %0, %1, %2;" : "=l"(s01) : "l"(a0), "l"(a1));
        asm("add.rn.f32x2 %0, %1, %2;" : "=l"(s23) : "l"(a2), "l"(a3));
        asm("add.rn.f32x2 %0, %1, %2;" : "=l"(sA)  : "l"(s01), "l"(s23));
        float lo, hi;
        asm("mov.b64 {%0,%1}, %2;" : "=f"(lo), "=f"(hi) : "l"(sA));
        float ghv = lo + hi;

        // r/z: finish gate pre-barrier (overlaps other warps' FMA issue)
        if (gate == 0) {
            rsh[hid] = __fdividef(1.f, 1.f + __expf(-(xv + ghv)));
        } else if (gate == 1) {
            zsh[hid] = __fdividef(1.f, 1.f + __expf(-(xv + ghv)));
        }
        __syncthreads();

        // n-threads: tanh + state update (h lives in their registers)
        if (gate == 2) {
            float r = rsh[hid], z = zsh[hid];
            float narg = xv + r * ghv;
            float e2 = __expf(2.f * narg);
            float n = 1.f - __fdividef(2.f, e2 + 1.f);
            hcur = n + z * (hcur - n);
            hsh[hid] = hcur;
        }
        __syncthreads();
    }
    if (gate == 2) g_hcat[b * HID + hid] = hcur;
}

// ---------------------------------------------------------------------------
__global__ __launch_bounds__(256) void head_kernel(
    const float* __restrict__ fc1_w, const float* __restrict__ fc1_b,
    const float* __restrict__ fc2_w, const float* __restrict__ fc2_b,
    float* __restrict__ out)
{
    __shared__ float hs[256], ys[256], ls[3];
    const int t = threadIdx.x;
    hs[t] = g_hcat[t];
    __syncthreads();

    float acc = fc1_b[t];
    #pragma unroll 8
    for (int j = 0; j < 256; j++) acc += fc1_w[t * 256 + j] * hs[j];
    ys[t] = fmaxf(acc, 0.f);
    __syncthreads();

    if (t < 3) {
        float a = fc2_b[t];
        for (int j = 0; j < 256; j++) a += fc2_w[t * 256 + j] * ys[j];
        ls[t] = a;
    }
    __syncthreads();

    if (t == 0) {
        float m = fmaxf(ls[0], fmaxf(ls[1], ls[2]));
        float s = expf(ls[0] - m) + expf(ls[1] - m) + expf(ls[2] - m);
        float lse = m + logf(s);
        out[0] = ls[0] - lse; out[1] = ls[1] - lse; out[2] = ls[2] - lse;
    }
}

// ---------------------------------------------------------------------------
extern "C" void kernel_launch(void* const* d_in, const int* in_sizes, int n_in,
                              void* d_out, int out_size)
{
    (void)in_sizes; (void)n_in; (void)out_size;

    const float* x1     = (const float*)d_in[0];
    const float* x2     = (const float*)d_in[1];
    const float* q_w    = (const float*)d_in[2];
    const float* q_b    = (const float*)d_in[3];
    const float* k_w    = (const float*)d_in[4];
    const float* k_b    = (const float*)d_in[5];
    const float* v_w    = (const float*)d_in[6];
    const float* v_b    = (const float*)d_in[7];
    const float* aln_g  = (const float*)d_in[8];
    const float* aln_b  = (const float*)d_in[9];
    const float* w_w    = (const float*)d_in[10];
    const float* w_b    = (const float*)d_in[11];
    const float* mln_g  = (const float*)d_in[12];
    const float* mln_b  = (const float*)d_in[13];
    const float* g1_wih = (const float*)d_in[14];
    const float* g1_whh = (const float*)d_in[15];
    const float* g1_bih = (const float*)d_in[16];
    const float* g1_bhh = (const float*)d_in[17];
    const float* g2_wih = (const float*)d_in[18];
    const float* g2_whh = (const float*)d_in[19];
    const float* g2_bih = (const float*)d_in[20];
    const float* g2_bhh = (const float*)d_in[21];
    const float* fc1_w  = (const float*)d_in[22];
    const float* fc1_b  = (const float*)d_in[23];
    const float* fc2_w  = (const float*)d_in[24];
    const float* fc2_b  = (const float*)d_in[25];
    float* out = (float*)d_out;

    void *pv;
    cudaGetSymbolAddress(&pv, g_x);      float* p_x      = (float*)pv;
    cudaGetSymbolAddress(&pv, g_cur);    float* p_cur    = (float*)pv;
    cudaGetSymbolAddress(&pv, g_qkv);    float* p_qkv    = (float*)pv;
    cudaGetSymbolAddress(&pv, g_vt);     float* p_vt     = (float*)pv;
    cudaGetSymbolAddress(&pv, g_attn);   float* p_attn   = (float*)pv;
    cudaGetSymbolAddress(&pv, g_h);      float* p_h      = (float*)pv;
    cudaGetSymbolAddress(&pv, g_tmp);    float* p_tmp    = (float*)pv;
    cudaGetSymbolAddress(&pv, g_scores); float* p_scores = (float*)pv;
    cudaGetSymbolAddress(&pv, g_avp);    float* p_avp    = (float*)pv;
    cudaGetSymbolAddress(&pv, g_gx);     float* p_gx     = (float*)pv;
    cudaGetSymbolAddress(&pv, g_wqkv);   float* p_wqkv   = (float*)pv;
    cudaGetSymbolAddress(&pv, g_bqkv);   float* p_bqkv   = (float*)pv;
    cudaGetSymbolAddress(&pv, g_wih);    float* p_wih    = (float*)pv;
    cudaGetSymbolAddress(&pv, g_bih);    float* p_bih    = (float*)pv;

    const ll SV = (ll)SEQ * VECT;
    const ll S9 = (ll)SEQ * 3 * VECT;
    const ll SS = (ll)SEQ * SEQ;
    const int N9 = 3 * VECT;
    const float inv_scale = 0.05773502691896258f;   // 1/sqrt(300)

    const int SMEM_MMA = 3 * (2 * 128 * 36) * 4;    // 110592 B
    cudaFuncSetAttribute(mma_bt<false>, cudaFuncAttributeMaxDynamicSharedMemorySize, SMEM_MMA);
    cudaFuncSetAttribute(mma_bt<true>,  cudaFuncAttributeMaxDynamicSharedMemorySize, SMEM_MMA);

    init_kernel<<<(2 * SEQ * VECT + 255) / 256, 256>>>(x1, x2);
    {
        int tot = 3 * VECT * VECT + 3 * VECT + 2 * G3 * VECT + 2 * G3;
        pack_kernel<<<(tot + 255) / 256, 256>>>(q_w, q_b, k_w, k_b, v_w, v_b,
                                                g1_wih, g1_bih, g2_wih, g2_bih);
    }

    dim3 gqkv(8, 32, 2);    // QKV proj: N=900 -> 8 tiles of 128
    dim3 gqk (32, 32, 2);   // QK^T: 4096x4096
    dim3 gavs(3, 32, 8);    // split-K A·V: z = seq*4 + split -> 768 CTAs
    dim3 gred(SEQ * VECT / 1024, 2);
    dim3 gw  (3, 32, 2);    // W proj
    dim3 gtr (10, 128, 2);  // V transpose

    for (int s = 0; s < NSTACK; s++) {
        mma_bt<false><<<gqkv, 256, SMEM_MMA>>>(p_cur, p_wqkv, p_qkv, SEQ, N9, VECT,
                                               VECT, VECT, N9, SV, 0, S9,
                                               p_bqkv, 0, 1.f);
        mma_bt<false><<<gqk, 256, SMEM_MMA>>>(p_qkv, p_qkv + VECT, p_scores, SEQ, SEQ, VECT,
                                              N9, N9, SEQ, S9, S9, SS,
                                              nullptr, 0, inv_scale);
        softmax_kernel<<<dim3(SEQ, 2), 256>>>(p_scores);

        transpose_kernel<<<gtr, 256>>>(p_qkv + 2 * VECT, p_vt, N9, S9, SV);
        // split-K A·V: 4 partial GEMMs in one launch, then reduce
        mma_bt<true><<<gavs, 256, SMEM_MMA>>>(p_scores, p_vt, p_avp, SEQ, VECT, KSPLIT,
                                              SEQ, SEQ, VECT, SS, SV, SV,
                                              nullptr, 0, 1.f);
        av_reduce_kernel<<<gred, 256>>>(p_avp, p_attn);

        ln_add_kernel<<<dim3(SEQ / 4, 2), 128>>>(p_attn, p_cur, aln_g, aln_b, p_h);
        mma_bt<false><<<gw, 256, SMEM_MMA>>>(p_h, w_w, p_tmp, SEQ, VECT, VECT,
                                             VECT, VECT, VECT, SV, 0, SV,
                                             w_b, 0, 1.f);
        ln_add_kernel<<<dim3(SEQ / 4, 2), 128>>>(p_tmp, p_x, mln_g, mln_b, p_cur);
    }

    dim3 gg(3, 32, 2);
    mma_bt<false><<<gg, 256, SMEM_MMA>>>(p_cur, p_wih, p_gx, SEQ, G3, VECT,
                                         VECT, VECT, G3, SV, (ll)G3 * VECT, (ll)SEQ * G3,
                                         p_bih, G3, 1.f);
    gru_kernel<<<2, 384>>>(g1_whh, g1_bhh, g2_whh, g2_bhh);
    head_kernel<<<1, 256>>>(fc1_w, fc1_b, fc2_w, fc2_b, out);
}